// round 2
// baseline (speedup 1.0000x reference)
#include <cuda_runtime.h>
#include <cuda_bf16.h>

// Problem constants
#define DMODEL 512
#define FFN    2048
#define NEXP   8
#define TOPK   2
#define NTOK   8192   // B*S = 2*4096
#define NROWS  (NTOK * TOPK)   // 16384 total expert-row assignments

// GEMM tiling
#define BM 128
#define BN 128
#define BK 8
#define TM 8
#define TN 8
#define NTHREADS 256

// Scratch (device globals — no dynamic allocation allowed).
// Compacted hidden: one row per (token, k) assignment -> 16384 x 2048 f32 = 128 MB.
__device__ float g_hidden[(size_t)NROWS * FFN];
__device__ int   g_cnt[NEXP];
__device__ int   g_off[NEXP];
__device__ int   g_tok[NROWS];     // token id per compacted row (grouped by expert)
__device__ float g_gate[NROWS];    // gate weight per compacted row
__device__ int   g_cursor[NEXP];   // scatter cursors

// ---------------------------------------------------------------------------
// Kernel 0: zero output + counters
// ---------------------------------------------------------------------------
__global__ void zero_kernel(float* __restrict__ out, int n) {
    int i = blockIdx.x * blockDim.x + threadIdx.x;
    if (i < NEXP) { g_cnt[i] = 0; g_cursor[i] = 0; }
    for (int j = i; j < n; j += gridDim.x * blockDim.x) out[j] = 0.0f;
}

// ---------------------------------------------------------------------------
// Kernel 1: router — one warp per token. logits = x@rw + rb; top-2 (strict >,
// ascending scan == jax top_k lowest-index tie-break); renormalized weights
// collapse to sigmoid of the logit difference. Counts per expert.
// Stores per-token picks in shared-nothing per-token arrays via g_tok later;
// here we just count, picks are recomputed cheaply? No — store them.
// ---------------------------------------------------------------------------
__device__ int   g_pick_e[NTOK * TOPK];
__device__ float g_pick_w[NTOK * TOPK];

__global__ void router_kernel(const float* __restrict__ x,
                              const float* __restrict__ rw,
                              const float* __restrict__ rb) {
    int warp = (blockIdx.x * blockDim.x + threadIdx.x) >> 5;
    int lane = threadIdx.x & 31;
    if (warp >= NTOK) return;
    const float* xr = x + (size_t)warp * DMODEL;
    float acc[NEXP];
#pragma unroll
    for (int e = 0; e < NEXP; e++) acc[e] = 0.0f;
    for (int d = lane; d < DMODEL; d += 32) {
        float xv = xr[d];
#pragma unroll
        for (int e = 0; e < NEXP; e++) acc[e] += xv * rw[d * NEXP + e];
    }
#pragma unroll
    for (int e = 0; e < NEXP; e++) {
#pragma unroll
        for (int o = 16; o > 0; o >>= 1) acc[e] += __shfl_xor_sync(0xffffffffu, acc[e], o);
    }
    if (lane == 0) {
        float l[NEXP];
#pragma unroll
        for (int e = 0; e < NEXP; e++) l[e] = acc[e] + rb[e];
        int i0 = 0;
#pragma unroll
        for (int e = 1; e < NEXP; e++) if (l[e] > l[i0]) i0 = e;
        int i1 = -1;
#pragma unroll
        for (int e = 0; e < NEXP; e++) {
            if (e == i0) continue;
            if (i1 < 0 || l[e] > l[i1]) i1 = e;
        }
        float z  = expf(l[i1] - l[i0]);     // <= 1
        float w0 = 1.0f / (1.0f + z);
        float w1 = z * w0;
        g_pick_e[warp * 2 + 0] = i0;
        g_pick_w[warp * 2 + 0] = w0;
        g_pick_e[warp * 2 + 1] = i1;
        g_pick_w[warp * 2 + 1] = w1;
        atomicAdd(&g_cnt[i0], 1);
        atomicAdd(&g_cnt[i1], 1);
    }
}

// ---------------------------------------------------------------------------
// Kernel 1b: exclusive prefix sum over 8 counters (single thread; trivial)
// ---------------------------------------------------------------------------
__global__ void offsets_kernel() {
    int s = 0;
#pragma unroll
    for (int e = 0; e < NEXP; e++) { g_off[e] = s; s += g_cnt[e]; }
}

// ---------------------------------------------------------------------------
// Kernel 1c: scatter token ids + gates into expert-grouped compact lists
// ---------------------------------------------------------------------------
__global__ void scatter_kernel() {
    int t = blockIdx.x * blockDim.x + threadIdx.x;
    if (t >= NTOK) return;
#pragma unroll
    for (int k = 0; k < TOPK; k++) {
        int e   = g_pick_e[t * 2 + k];
        int pos = atomicAdd(&g_cursor[e], 1);
        int row = g_off[e] + pos;
        g_tok[row]  = t;
        g_gate[row] = g_pick_w[t * 2 + k];
    }
}

// ---------------------------------------------------------------------------
// Kernel 2: GEMM1 (gathered): hidden[row] = relu(x[tok[row]] @ w1[e] + b1[e])
// ---------------------------------------------------------------------------
__global__ __launch_bounds__(NTHREADS)
void gemm1_kernel(const float* __restrict__ x,
                  const float* __restrict__ w1,
                  const float* __restrict__ b1) {
    int e = blockIdx.z;
    int cnt = g_cnt[e];
    int tileM = blockIdx.y;
    if (tileM * BM >= cnt) return;
    int tileN = blockIdx.x;
    int base = g_off[e];

    const float* W = w1 + (size_t)e * DMODEL * FFN;
    __shared__ float As[BK][BM];
    __shared__ float Bs[BK][BN];

    int tid  = threadIdx.x;
    int arow = tid >> 1;
    int acol = (tid & 1) * 4;
    int brow = tid >> 5;
    int bcol = (tid & 31) * 4;
    int trow = tid >> 4;
    int tcol = tid & 15;

    int mg = tileM * BM + arow;
    if (mg >= cnt) mg = cnt - 1;
    const float* Arow = x + (size_t)g_tok[base + mg] * DMODEL;

    float acc[TM][TN];
#pragma unroll
    for (int i = 0; i < TM; i++)
#pragma unroll
        for (int j = 0; j < TN; j++) acc[i][j] = 0.0f;

    for (int k0 = 0; k0 < DMODEL; k0 += BK) {
        float4 av = *(const float4*)(Arow + k0 + acol);
        As[acol + 0][arow] = av.x;
        As[acol + 1][arow] = av.y;
        As[acol + 2][arow] = av.z;
        As[acol + 3][arow] = av.w;
        *(float4*)&Bs[brow][bcol] =
            *(const float4*)(W + (size_t)(k0 + brow) * FFN + tileN * BN + bcol);
        __syncthreads();
#pragma unroll
        for (int k = 0; k < BK; k++) {
            float4 a0 = *(const float4*)&As[k][trow * TM];
            float4 a1 = *(const float4*)&As[k][trow * TM + 4];
            float4 b0 = *(const float4*)&Bs[k][tcol * TN];
            float4 b1v = *(const float4*)&Bs[k][tcol * TN + 4];
            float ra[TM] = {a0.x, a0.y, a0.z, a0.w, a1.x, a1.y, a1.z, a1.w};
            float rb[TN] = {b0.x, b0.y, b0.z, b0.w, b1v.x, b1v.y, b1v.z, b1v.w};
#pragma unroll
            for (int i = 0; i < TM; i++)
#pragma unroll
                for (int j = 0; j < TN; j++) acc[i][j] += ra[i] * rb[j];
        }
        __syncthreads();
    }

    int ncol = tileN * BN + tcol * TN;
#pragma unroll
    for (int i = 0; i < TM; i++) {
        int m = tileM * BM + trow * TM + i;
        if (m < cnt) {
            float* Hrow = g_hidden + (size_t)(base + m) * FFN + ncol;
#pragma unroll
            for (int j = 0; j < TN; j++) {
                float v = acc[i][j] + b1[e * FFN + ncol + j];
                Hrow[j] = v > 0.0f ? v : 0.0f;
            }
        }
    }
}

// ---------------------------------------------------------------------------
// Kernel 3: GEMM2: out[tok[row]] += gate[row] * (hidden[row] @ w2[e] + b2[e])
// ---------------------------------------------------------------------------
__global__ __launch_bounds__(NTHREADS)
void gemm2_kernel(const float* __restrict__ w2,
                  const float* __restrict__ b2,
                  float* __restrict__ out) {
    int e = blockIdx.z;
    int cnt = g_cnt[e];
    int tileM = blockIdx.y;
    if (tileM * BM >= cnt) return;
    int tileN = blockIdx.x;
    int base = g_off[e];

    const float* W = w2 + (size_t)e * FFN * DMODEL;
    __shared__ float As[BK][BM];
    __shared__ float Bs[BK][BN];

    int tid  = threadIdx.x;
    int arow = tid >> 1;
    int acol = (tid & 1) * 4;
    int brow = tid >> 5;
    int bcol = (tid & 31) * 4;
    int trow = tid >> 4;
    int tcol = tid & 15;

    int mg = tileM * BM + arow;
    if (mg >= cnt) mg = cnt - 1;
    const float* Arow = g_hidden + (size_t)(base + mg) * FFN;

    float acc[TM][TN];
#pragma unroll
    for (int i = 0; i < TM; i++)
#pragma unroll
        for (int j = 0; j < TN; j++) acc[i][j] = 0.0f;

    for (int k0 = 0; k0 < FFN; k0 += BK) {
        float4 av = *(const float4*)(Arow + k0 + acol);
        As[acol + 0][arow] = av.x;
        As[acol + 1][arow] = av.y;
        As[acol + 2][arow] = av.z;
        As[acol + 3][arow] = av.w;
        *(float4*)&Bs[brow][bcol] =
            *(const float4*)(W + (size_t)(k0 + brow) * DMODEL + tileN * BN + bcol);
        __syncthreads();
#pragma unroll
        for (int k = 0; k < BK; k++) {
            float4 a0 = *(const float4*)&As[k][trow * TM];
            float4 a1 = *(const float4*)&As[k][trow * TM + 4];
            float4 b0 = *(const float4*)&Bs[k][tcol * TN];
            float4 b1v = *(const float4*)&Bs[k][tcol * TN + 4];
            float ra[TM] = {a0.x, a0.y, a0.z, a0.w, a1.x, a1.y, a1.z, a1.w};
            float rb[TN] = {b0.x, b0.y, b0.z, b0.w, b1v.x, b1v.y, b1v.z, b1v.w};
#pragma unroll
            for (int i = 0; i < TM; i++)
#pragma unroll
                for (int j = 0; j < TN; j++) acc[i][j] += ra[i] * rb[j];
        }
        __syncthreads();
    }

    int ncol = tileN * BN + tcol * TN;
#pragma unroll
    for (int i = 0; i < TM; i++) {
        int m = tileM * BM + trow * TM + i;
        if (m < cnt) {
            int   token = g_tok[base + m];
            float gate  = g_gate[base + m];
            float* orow = out + (size_t)token * DMODEL + ncol;
#pragma unroll
            for (int j = 0; j < TN; j++) {
                float v = (acc[i][j] + b2[e * DMODEL + ncol + j]) * gate;
                atomicAdd(&orow[j], v);
            }
        }
    }
}

// ---------------------------------------------------------------------------
// kernel_launch
// Inputs: 0:x [2,4096,512] f32, 1:router_w [512,8], 2:router_b [8],
//         3:w1 [8,512,2048], 4:b1 [8,2048], 5:w2 [8,2048,512], 6:b2 [8,512]
// Output: [2,4096,512] f32
// ---------------------------------------------------------------------------
extern "C" void kernel_launch(void* const* d_in, const int* in_sizes, int n_in,
                              void* d_out, int out_size) {
    const float* x   = (const float*)d_in[0];
    const float* rw  = (const float*)d_in[1];
    const float* rb  = (const float*)d_in[2];
    const float* w1  = (const float*)d_in[3];
    const float* b1  = (const float*)d_in[4];
    const float* w2  = (const float*)d_in[5];
    const float* b2  = (const float*)d_in[6];
    float* out = (float*)d_out;

    int nout = NTOK * DMODEL;
    zero_kernel<<<1024, 256>>>(out, nout);

    router_kernel<<<(NTOK * 32) / 256, 256>>>(x, rw, rb);   // one warp/token
    offsets_kernel<<<1, 1>>>();
    scatter_kernel<<<NTOK / 256, 256>>>();

    dim3 g1(FFN / BN, NTOK / BM, NEXP);    // 16 x 64 x 8, most tiles early-exit
    gemm1_kernel<<<g1, NTHREADS>>>(x, w1, b1);

    dim3 g2(DMODEL / BN, NTOK / BM, NEXP); // 4 x 64 x 8
    gemm2_kernel<<<g2, NTHREADS>>>(w2, b2, out);
}

// round 3
// speedup vs baseline: 1.0573x; 1.0573x over previous
#include <cuda_runtime.h>
#include <cuda_bf16.h>

// Problem constants
#define DMODEL 512
#define FFN    2048
#define NEXP   8
#define TOPK   2
#define NTOK   8192   // B*S
#define NROWS  (NTOK * TOPK)

// GEMM tiling
#define BM 128
#define BN 128
#define BK 8
#define TM 8
#define TN 8
#define NTHREADS 256

// f32x2 packed-FMA helpers (Blackwell FFMA2 — 2 fp32 FMAs per issue slot)
#define FFMA2(d, a, b) \
    asm("fma.rn.f32x2 %0, %1, %2, %0;" : "+l"(d) : "l"(a), "l"(b))
#define PACKDUP(d, s) \
    asm("mov.b64 %0, {%1, %1};" : "=l"(d) : "r"(__float_as_uint(s)))
#define UNPACK2(lo, hi, v) \
    asm("mov.b64 {%0, %1}, %2;" : "=f"(lo), "=f"(hi) : "l"(v))

// Scratch (device globals — no dynamic allocation allowed). 128 MB hidden.
__device__ float g_hidden[(size_t)NROWS * FFN];
__device__ int   g_cnt[NEXP];
__device__ int   g_off[NEXP];
__device__ int   g_tok[NROWS];
__device__ float g_gate[NROWS];
__device__ int   g_cursor[NEXP];
__device__ int   g_pick_e[NTOK * TOPK];
__device__ float g_pick_w[NTOK * TOPK];

// ---------------------------------------------------------------------------
__global__ void zero_kernel(float* __restrict__ out, int n) {
    int i = blockIdx.x * blockDim.x + threadIdx.x;
    if (i < NEXP) { g_cnt[i] = 0; g_cursor[i] = 0; }
    float4* o4 = (float4*)out;
    int n4 = n >> 2;
    float4 z = make_float4(0.f, 0.f, 0.f, 0.f);
    for (int j = i; j < n4; j += gridDim.x * blockDim.x) o4[j] = z;
}

// ---------------------------------------------------------------------------
// Router: one warp per token. top-2 via strict > ascending scan (jax
// lowest-index tie-break); renormalized top-2 softmax = sigmoid of logit gap.
// ---------------------------------------------------------------------------
__global__ void router_kernel(const float* __restrict__ x,
                              const float* __restrict__ rw,
                              const float* __restrict__ rb) {
    int warp = (blockIdx.x * blockDim.x + threadIdx.x) >> 5;
    int lane = threadIdx.x & 31;
    if (warp >= NTOK) return;
    const float* xr = x + (size_t)warp * DMODEL;
    float acc[NEXP];
#pragma unroll
    for (int e = 0; e < NEXP; e++) acc[e] = 0.0f;
    for (int d = lane; d < DMODEL; d += 32) {
        float xv = xr[d];
#pragma unroll
        for (int e = 0; e < NEXP; e++) acc[e] += xv * rw[d * NEXP + e];
    }
#pragma unroll
    for (int e = 0; e < NEXP; e++) {
#pragma unroll
        for (int o = 16; o > 0; o >>= 1) acc[e] += __shfl_xor_sync(0xffffffffu, acc[e], o);
    }
    if (lane == 0) {
        float l[NEXP];
#pragma unroll
        for (int e = 0; e < NEXP; e++) l[e] = acc[e] + rb[e];
        int i0 = 0;
#pragma unroll
        for (int e = 1; e < NEXP; e++) if (l[e] > l[i0]) i0 = e;
        int i1 = -1;
#pragma unroll
        for (int e = 0; e < NEXP; e++) {
            if (e == i0) continue;
            if (i1 < 0 || l[e] > l[i1]) i1 = e;
        }
        float z  = expf(l[i1] - l[i0]);
        float w0 = 1.0f / (1.0f + z);
        float w1 = z * w0;
        g_pick_e[warp * 2 + 0] = i0;
        g_pick_w[warp * 2 + 0] = w0;
        g_pick_e[warp * 2 + 1] = i1;
        g_pick_w[warp * 2 + 1] = w1;
        atomicAdd(&g_cnt[i0], 1);
        atomicAdd(&g_cnt[i1], 1);
    }
}

__global__ void offsets_kernel() {
    int s = 0;
#pragma unroll
    for (int e = 0; e < NEXP; e++) { g_off[e] = s; s += g_cnt[e]; }
}

__global__ void scatter_kernel() {
    int t = blockIdx.x * blockDim.x + threadIdx.x;
    if (t >= NTOK) return;
#pragma unroll
    for (int k = 0; k < TOPK; k++) {
        int e   = g_pick_e[t * 2 + k];
        int pos = atomicAdd(&g_cursor[e], 1);
        int row = g_off[e] + pos;
        g_tok[row]  = t;
        g_gate[row] = g_pick_w[t * 2 + k];
    }
}

// ---------------------------------------------------------------------------
// GEMM1 (gathered): hidden[row] = relu(x[tok[row]] @ w1[e] + b1[e])
// f32x2 packed FMAs: acc pairs along N.
// ---------------------------------------------------------------------------
__global__ __launch_bounds__(NTHREADS)
void gemm1_kernel(const float* __restrict__ x,
                  const float* __restrict__ w1,
                  const float* __restrict__ b1) {
    int e = blockIdx.z;
    int cnt = g_cnt[e];
    int tileM = blockIdx.y;
    if (tileM * BM >= cnt) return;
    int tileN = blockIdx.x;
    int base = g_off[e];

    const float* W = w1 + (size_t)e * DMODEL * FFN;
    __shared__ __align__(16) float As[BK][BM];
    __shared__ __align__(16) float Bs[BK][BN];

    int tid  = threadIdx.x;
    int arow = tid >> 1;
    int acol = (tid & 1) * 4;
    int brow = tid >> 5;
    int bcol = (tid & 31) * 4;
    int trow = tid >> 4;
    int tcol = tid & 15;

    int mg = tileM * BM + arow;
    if (mg >= cnt) mg = cnt - 1;
    const float* Arow = x + (size_t)g_tok[base + mg] * DMODEL;

    unsigned long long acc2[TM][TN / 2];
#pragma unroll
    for (int i = 0; i < TM; i++)
#pragma unroll
        for (int jp = 0; jp < TN / 2; jp++) acc2[i][jp] = 0ull;

    for (int k0 = 0; k0 < DMODEL; k0 += BK) {
        float4 av = *(const float4*)(Arow + k0 + acol);
        As[acol + 0][arow] = av.x;
        As[acol + 1][arow] = av.y;
        As[acol + 2][arow] = av.z;
        As[acol + 3][arow] = av.w;
        *(float4*)&Bs[brow][bcol] =
            *(const float4*)(W + (size_t)(k0 + brow) * FFN + tileN * BN + bcol);
        __syncthreads();
#pragma unroll
        for (int k = 0; k < BK; k++) {
            float4 a0 = *(const float4*)&As[k][trow * TM];
            float4 a1 = *(const float4*)&As[k][trow * TM + 4];
            ulonglong2 bq0 = *(const ulonglong2*)&Bs[k][tcol * TN];
            ulonglong2 bq1 = *(const ulonglong2*)&Bs[k][tcol * TN + 4];
            unsigned long long bb[4] = {bq0.x, bq0.y, bq1.x, bq1.y};
            float ra[TM] = {a0.x, a0.y, a0.z, a0.w, a1.x, a1.y, a1.z, a1.w};
#pragma unroll
            for (int i = 0; i < TM; i++) {
                unsigned long long a2;
                PACKDUP(a2, ra[i]);
#pragma unroll
                for (int jp = 0; jp < TN / 2; jp++) FFMA2(acc2[i][jp], a2, bb[jp]);
            }
        }
        __syncthreads();
    }

    int ncol = tileN * BN + tcol * TN;
    float4 bia0 = *(const float4*)(b1 + e * FFN + ncol);
    float4 bia1 = *(const float4*)(b1 + e * FFN + ncol + 4);
    float bias[TN] = {bia0.x, bia0.y, bia0.z, bia0.w, bia1.x, bia1.y, bia1.z, bia1.w};
#pragma unroll
    for (int i = 0; i < TM; i++) {
        int m = tileM * BM + trow * TM + i;
        if (m < cnt) {
            float v[TN];
#pragma unroll
            for (int jp = 0; jp < TN / 2; jp++)
                UNPACK2(v[2 * jp], v[2 * jp + 1], acc2[i][jp]);
            float4 o0, o1;
            o0.x = fmaxf(v[0] + bias[0], 0.f);
            o0.y = fmaxf(v[1] + bias[1], 0.f);
            o0.z = fmaxf(v[2] + bias[2], 0.f);
            o0.w = fmaxf(v[3] + bias[3], 0.f);
            o1.x = fmaxf(v[4] + bias[4], 0.f);
            o1.y = fmaxf(v[5] + bias[5], 0.f);
            o1.z = fmaxf(v[6] + bias[6], 0.f);
            o1.w = fmaxf(v[7] + bias[7], 0.f);
            float* Hrow = g_hidden + (size_t)(base + m) * FFN + ncol;
            *(float4*)(Hrow)     = o0;
            *(float4*)(Hrow + 4) = o1;
        }
    }
}

// ---------------------------------------------------------------------------
// GEMM2: out[tok[row]] += gate[row] * (hidden[row] @ w2[e] + b2[e])
// ---------------------------------------------------------------------------
__global__ __launch_bounds__(NTHREADS)
void gemm2_kernel(const float* __restrict__ w2,
                  const float* __restrict__ b2,
                  float* __restrict__ out) {
    int e = blockIdx.z;
    int cnt = g_cnt[e];
    int tileM = blockIdx.y;
    if (tileM * BM >= cnt) return;
    int tileN = blockIdx.x;
    int base = g_off[e];

    const float* W = w2 + (size_t)e * FFN * DMODEL;
    __shared__ __align__(16) float As[BK][BM];
    __shared__ __align__(16) float Bs[BK][BN];

    int tid  = threadIdx.x;
    int arow = tid >> 1;
    int acol = (tid & 1) * 4;
    int brow = tid >> 5;
    int bcol = (tid & 31) * 4;
    int trow = tid >> 4;
    int tcol = tid & 15;

    int mg = tileM * BM + arow;
    if (mg >= cnt) mg = cnt - 1;
    const float* Arow = g_hidden + (size_t)(base + mg) * FFN;

    unsigned long long acc2[TM][TN / 2];
#pragma unroll
    for (int i = 0; i < TM; i++)
#pragma unroll
        for (int jp = 0; jp < TN / 2; jp++) acc2[i][jp] = 0ull;

    for (int k0 = 0; k0 < FFN; k0 += BK) {
        float4 av = *(const float4*)(Arow + k0 + acol);
        As[acol + 0][arow] = av.x;
        As[acol + 1][arow] = av.y;
        As[acol + 2][arow] = av.z;
        As[acol + 3][arow] = av.w;
        *(float4*)&Bs[brow][bcol] =
            *(const float4*)(W + (size_t)(k0 + brow) * DMODEL + tileN * BN + bcol);
        __syncthreads();
#pragma unroll
        for (int k = 0; k < BK; k++) {
            float4 a0 = *(const float4*)&As[k][trow * TM];
            float4 a1 = *(const float4*)&As[k][trow * TM + 4];
            ulonglong2 bq0 = *(const ulonglong2*)&Bs[k][tcol * TN];
            ulonglong2 bq1 = *(const ulonglong2*)&Bs[k][tcol * TN + 4];
            unsigned long long bb[4] = {bq0.x, bq0.y, bq1.x, bq1.y};
            float ra[TM] = {a0.x, a0.y, a0.z, a0.w, a1.x, a1.y, a1.z, a1.w};
#pragma unroll
            for (int i = 0; i < TM; i++) {
                unsigned long long a2;
                PACKDUP(a2, ra[i]);
#pragma unroll
                for (int jp = 0; jp < TN / 2; jp++) FFMA2(acc2[i][jp], a2, bb[jp]);
            }
        }
        __syncthreads();
    }

    int ncol = tileN * BN + tcol * TN;
    float4 bia0 = *(const float4*)(b2 + e * DMODEL + ncol);
    float4 bia1 = *(const float4*)(b2 + e * DMODEL + ncol + 4);
    float bias[TN] = {bia0.x, bia0.y, bia0.z, bia0.w, bia1.x, bia1.y, bia1.z, bia1.w};
#pragma unroll
    for (int i = 0; i < TM; i++) {
        int m = tileM * BM + trow * TM + i;
        if (m < cnt) {
            int   token = g_tok[base + m];
            float gate  = g_gate[base + m];
            float* orow = out + (size_t)token * DMODEL + ncol;
            float v[TN];
#pragma unroll
            for (int jp = 0; jp < TN / 2; jp++)
                UNPACK2(v[2 * jp], v[2 * jp + 1], acc2[i][jp]);
#pragma unroll
            for (int j = 0; j < TN; j++)
                atomicAdd(&orow[j], (v[j] + bias[j]) * gate);
        }
    }
}

// ---------------------------------------------------------------------------
extern "C" void kernel_launch(void* const* d_in, const int* in_sizes, int n_in,
                              void* d_out, int out_size) {
    const float* x   = (const float*)d_in[0];
    const float* rw  = (const float*)d_in[1];
    const float* rb  = (const float*)d_in[2];
    const float* w1  = (const float*)d_in[3];
    const float* b1  = (const float*)d_in[4];
    const float* w2  = (const float*)d_in[5];
    const float* b2  = (const float*)d_in[6];
    float* out = (float*)d_out;

    zero_kernel<<<1024, 256>>>(out, NTOK * DMODEL);
    router_kernel<<<(NTOK * 32) / 256, 256>>>(x, rw, rb);
    offsets_kernel<<<1, 1>>>();
    scatter_kernel<<<NTOK / 256, 256>>>();

    dim3 g1(FFN / BN, NTOK / BM, NEXP);
    gemm1_kernel<<<g1, NTHREADS>>>(x, w1, b1);

    dim3 g2(DMODEL / BN, NTOK / BM, NEXP);
    gemm2_kernel<<<g2, NTHREADS>>>(w2, b2, out);
}

// round 6
// speedup vs baseline: 1.6159x; 1.5284x over previous
#include <cuda_runtime.h>
#include <cuda_bf16.h>
#include <cstdint>

// Problem constants
#define DMODEL 512
#define FFN    2048
#define NEXP   8
#define TOPK   2
#define NTOK   8192
#define NROWS  (NTOK * TOPK)
#define TILE   128
#define BK     32          // bf16 K elems per smem chunk
#define PAD    40          // smem row stride in bf16 elems (80 B, conflict-free)

// ---------------------------------------------------------------------------
// Device scratch (static). ~208 MB total.
// ---------------------------------------------------------------------------
__device__ __nv_bfloat16 g_xh[(size_t)NTOK * DMODEL];
__device__ __nv_bfloat16 g_xl[(size_t)NTOK * DMODEL];
__device__ __nv_bfloat16 g_w1h[(size_t)NEXP * FFN * DMODEL];   // [E][F][D]
__device__ __nv_bfloat16 g_w1l[(size_t)NEXP * FFN * DMODEL];
__device__ __nv_bfloat16 g_w2h[(size_t)NEXP * DMODEL * FFN];   // [E][D][F]
__device__ __nv_bfloat16 g_w2l[(size_t)NEXP * DMODEL * FFN];
__device__ __nv_bfloat16 g_hh[(size_t)NROWS * FFN];
__device__ __nv_bfloat16 g_hl[(size_t)NROWS * FFN];
__device__ int   g_cnt[NEXP];
__device__ int   g_off[NEXP];
__device__ int   g_cursor[NEXP];
__device__ int   g_tok[NROWS];
__device__ float g_gate[NROWS];
__device__ int   g_pick_e[NROWS];
__device__ float g_pick_w[NROWS];

// ---------------------------------------------------------------------------
__device__ __forceinline__ uint32_t smem_u32(const void* p) {
    uint32_t a;
    asm("{ .reg .u64 t; cvta.to.shared.u64 t, %1; cvt.u32.u64 %0, t; }" : "=r"(a) : "l"(p));
    return a;
}

#define LDSM4(R0, R1, R2, R3, ADDR) \
    asm volatile("ldmatrix.sync.aligned.m8n8.x4.shared.b16 {%0,%1,%2,%3}, [%4];" \
                 : "=r"(R0), "=r"(R1), "=r"(R2), "=r"(R3) : "r"(ADDR))

#define MMA16816(C, A, B0, B1) \
    asm volatile("mma.sync.aligned.m16n8k16.row.col.f32.bf16.bf16.f32 " \
                 "{%0,%1,%2,%3}, {%4,%5,%6,%7}, {%8,%9}, {%0,%1,%2,%3};" \
                 : "+f"((C)[0]), "+f"((C)[1]), "+f"((C)[2]), "+f"((C)[3]) \
                 : "r"((A)[0]), "r"((A)[1]), "r"((A)[2]), "r"((A)[3]), "r"(B0), "r"(B1))

// ---------------------------------------------------------------------------
__global__ void zero_kernel(float* __restrict__ out, int n) {
    int i = blockIdx.x * blockDim.x + threadIdx.x;
    if (i < NEXP) { g_cnt[i] = 0; g_cursor[i] = 0; }
    float4* o4 = (float4*)out;
    int n4 = n >> 2;
    float4 z = make_float4(0.f, 0.f, 0.f, 0.f);
    for (int j = i; j < n4; j += gridDim.x * blockDim.x) o4[j] = z;
}

// x -> bf16 hi/lo  (writes device globals directly — device code only)
__global__ void convert_x_kernel(const float* __restrict__ x) {
    int tot = NTOK * DMODEL / 4;
    for (int i = blockIdx.x * blockDim.x + threadIdx.x; i < tot; i += gridDim.x * blockDim.x) {
        float4 v = ((const float4*)x)[i];
        __nv_bfloat16 h0 = __float2bfloat16(v.x), h1 = __float2bfloat16(v.y);
        __nv_bfloat16 h2 = __float2bfloat16(v.z), h3 = __float2bfloat16(v.w);
        __nv_bfloat162* ph = (__nv_bfloat162*)(g_xh + (size_t)i * 4);
        ph[0] = __halves2bfloat162(h0, h1);
        ph[1] = __halves2bfloat162(h2, h3);
        __nv_bfloat162* pl = (__nv_bfloat162*)(g_xl + (size_t)i * 4);
        pl[0] = __halves2bfloat162(__float2bfloat16(v.x - __bfloat162float(h0)),
                                   __float2bfloat16(v.y - __bfloat162float(h1)));
        pl[1] = __halves2bfloat162(__float2bfloat16(v.z - __bfloat162float(h2)),
                                   __float2bfloat16(v.w - __bfloat162float(h3)));
    }
}

// Transpose-convert core. dst selected INSIDE device code (device globals must
// never be passed as kernel args from host — host sees only shadow symbols).
__device__ __forceinline__ void transconv_body(const float* __restrict__ w,
                                               __nv_bfloat16* __restrict__ oh,
                                               __nv_bfloat16* __restrict__ ol,
                                               int K, int N) {
    __shared__ float t[32][33];
    int e = blockIdx.z;
    const float* we = w + (size_t)e * K * N;
    int n0 = blockIdx.x * 32, k0 = blockIdx.y * 32;
    int tx = threadIdx.x, ty = threadIdx.y;
    for (int i = ty; i < 32; i += 8)
        t[i][tx] = we[(size_t)(k0 + i) * N + n0 + tx];
    __syncthreads();
    size_t ob = (size_t)e * N * K;
    for (int i = ty; i < 32; i += 8) {
        float v = t[tx][i];
        __nv_bfloat16 h = __float2bfloat16(v);
        size_t o = ob + (size_t)(n0 + i) * K + k0 + tx;
        oh[o] = h;
        ol[o] = __float2bfloat16(v - __bfloat162float(h));
    }
}

__global__ void transconv_w1_kernel(const float* __restrict__ w1) {
    transconv_body(w1, g_w1h, g_w1l, DMODEL, FFN);
}
__global__ void transconv_w2_kernel(const float* __restrict__ w2) {
    transconv_body(w2, g_w2h, g_w2l, FFN, DMODEL);
}

// ---------------------------------------------------------------------------
// Router / offsets / scatter (validated)
// ---------------------------------------------------------------------------
__global__ void router_kernel(const float* __restrict__ x,
                              const float* __restrict__ rw,
                              const float* __restrict__ rb) {
    int warp = (blockIdx.x * blockDim.x + threadIdx.x) >> 5;
    int lane = threadIdx.x & 31;
    if (warp >= NTOK) return;
    const float* xr = x + (size_t)warp * DMODEL;
    float acc[NEXP];
#pragma unroll
    for (int e = 0; e < NEXP; e++) acc[e] = 0.0f;
    for (int d = lane; d < DMODEL; d += 32) {
        float xv = xr[d];
#pragma unroll
        for (int e = 0; e < NEXP; e++) acc[e] += xv * rw[d * NEXP + e];
    }
#pragma unroll
    for (int e = 0; e < NEXP; e++) {
#pragma unroll
        for (int o = 16; o > 0; o >>= 1) acc[e] += __shfl_xor_sync(0xffffffffu, acc[e], o);
    }
    if (lane == 0) {
        float l[NEXP];
#pragma unroll
        for (int e = 0; e < NEXP; e++) l[e] = acc[e] + rb[e];
        int i0 = 0;
#pragma unroll
        for (int e = 1; e < NEXP; e++) if (l[e] > l[i0]) i0 = e;
        int i1 = -1;
#pragma unroll
        for (int e = 0; e < NEXP; e++) {
            if (e == i0) continue;
            if (i1 < 0 || l[e] > l[i1]) i1 = e;
        }
        float z  = expf(l[i1] - l[i0]);
        float w0 = 1.0f / (1.0f + z);
        float w1 = z * w0;
        g_pick_e[warp * 2 + 0] = i0;  g_pick_w[warp * 2 + 0] = w0;
        g_pick_e[warp * 2 + 1] = i1;  g_pick_w[warp * 2 + 1] = w1;
        atomicAdd(&g_cnt[i0], 1);
        atomicAdd(&g_cnt[i1], 1);
    }
}

__global__ void offsets_kernel() {
    int s = 0;
#pragma unroll
    for (int e = 0; e < NEXP; e++) { g_off[e] = s; s += g_cnt[e]; }
}

__global__ void scatter_kernel() {
    int t = blockIdx.x * blockDim.x + threadIdx.x;
    if (t >= NTOK) return;
#pragma unroll
    for (int k = 0; k < TOPK; k++) {
        int e   = g_pick_e[t * 2 + k];
        int pos = atomicAdd(&g_cursor[e], 1);
        int row = g_off[e] + pos;
        g_tok[row]  = t;
        g_gate[row] = g_pick_w[t * 2 + k];
    }
}

// ---------------------------------------------------------------------------
// Shared GEMM core: 128x128 tile, 8 warps (4M x 2N), warp tile 32x64,
// split-bf16 3-pass HMMA (AhBh + AlBh + AhBl), fp32 accum.
// ---------------------------------------------------------------------------
struct __align__(16) Smem {
    __nv_bfloat16 Ah[TILE * PAD];
    __nv_bfloat16 Al[TILE * PAD];
    __nv_bfloat16 Bh[TILE * PAD];
    __nv_bfloat16 Bl[TILE * PAD];
    int tok[TILE];
};

__device__ __forceinline__ void gemm_chunk_compute(
    uint32_t sAh, uint32_t sAl, uint32_t sBh, uint32_t sBl,
    int warpM, int warpN, int lane, float acc[2][8][4]) {
    int r16 = lane & 15;
    int c8  = (lane >> 4) * 8;
#pragma unroll
    for (int ks = 0; ks < 2; ks++) {
        int kb = ks * 16 + c8;
        uint32_t ah[2][4], al[2][4], bb[8][2];
#pragma unroll
        for (int mf = 0; mf < 2; mf++) {
            uint32_t off = ((warpM * 32 + mf * 16 + r16) * PAD + kb) * 2;
            LDSM4(ah[mf][0], ah[mf][1], ah[mf][2], ah[mf][3], sAh + off);
            LDSM4(al[mf][0], al[mf][1], al[mf][2], al[mf][3], sAl + off);
        }
#pragma unroll
        for (int nq = 0; nq < 4; nq++) {
            uint32_t off = ((warpN * 64 + nq * 16 + r16) * PAD + kb) * 2;
            uint32_t r0, r1, r2, r3;
            LDSM4(r0, r1, r2, r3, sBh + off);
            bb[2 * nq][0] = r0; bb[2 * nq][1] = r2;
            bb[2 * nq + 1][0] = r1; bb[2 * nq + 1][1] = r3;
        }
#pragma unroll
        for (int mf = 0; mf < 2; mf++)
#pragma unroll
            for (int nf = 0; nf < 8; nf++) {
                MMA16816(acc[mf][nf], ah[mf], bb[nf][0], bb[nf][1]);
                MMA16816(acc[mf][nf], al[mf], bb[nf][0], bb[nf][1]);
            }
#pragma unroll
        for (int nq = 0; nq < 4; nq++) {
            uint32_t off = ((warpN * 64 + nq * 16 + r16) * PAD + kb) * 2;
            uint32_t r0, r1, r2, r3;
            LDSM4(r0, r1, r2, r3, sBl + off);
            bb[2 * nq][0] = r0; bb[2 * nq][1] = r2;
            bb[2 * nq + 1][0] = r1; bb[2 * nq + 1][1] = r3;
        }
#pragma unroll
        for (int mf = 0; mf < 2; mf++)
#pragma unroll
            for (int nf = 0; nf < 8; nf++)
                MMA16816(acc[mf][nf], ah[mf], bb[nf][0], bb[nf][1]);
    }
}

// ---------------------------------------------------------------------------
// GEMM1 (HMMA): hidden[row] = relu(x[tok[row]] @ w1[e] + b1[e]); emit bf16 hi/lo
// ---------------------------------------------------------------------------
__global__ __launch_bounds__(256)
void gemm1_mma(const float* __restrict__ b1) {
    int e = blockIdx.z;
    int cnt = g_cnt[e];
    int tm = blockIdx.y;
    if (tm * TILE >= cnt) return;
    int tn = blockIdx.x;
    int base = g_off[e];

    __shared__ Smem sm;
    int tid = threadIdx.x, wid = tid >> 5, lane = tid & 31;
    int warpM = wid & 3, warpN = wid >> 2;

    if (tid < TILE) {
        int m = tm * TILE + tid;
        if (m >= cnt) m = cnt - 1;
        sm.tok[tid] = g_tok[base + m];
    }
    __syncthreads();

    uint32_t sAh = smem_u32(sm.Ah), sAl = smem_u32(sm.Al);
    uint32_t sBh = smem_u32(sm.Bh), sBl = smem_u32(sm.Bl);

    const __nv_bfloat16* Bhg = g_w1h + (size_t)e * FFN * DMODEL + (size_t)tn * TILE * DMODEL;
    const __nv_bfloat16* Blg = g_w1l + (size_t)e * FFN * DMODEL + (size_t)tn * TILE * DMODEL;

    float acc[2][8][4];
#pragma unroll
    for (int i = 0; i < 2; i++)
#pragma unroll
        for (int j = 0; j < 8; j++)
#pragma unroll
            for (int c = 0; c < 4; c++) acc[i][j][c] = 0.f;

    for (int ch = 0; ch < DMODEL / BK; ch++) {
        int koff = ch * BK;
#pragma unroll
        for (int u = tid; u < 512; u += 256) {
            int r = u >> 2, j = u & 3;
            uint32_t so = r * PAD + j * 8;
            size_t ao = (size_t)sm.tok[r] * DMODEL + koff + j * 8;
            *(uint4*)(sm.Ah + so) = *(const uint4*)(g_xh + ao);
            *(uint4*)(sm.Al + so) = *(const uint4*)(g_xl + ao);
            size_t bo = (size_t)r * DMODEL + koff + j * 8;
            *(uint4*)(sm.Bh + so) = *(const uint4*)(Bhg + bo);
            *(uint4*)(sm.Bl + so) = *(const uint4*)(Blg + bo);
        }
        __syncthreads();
        gemm_chunk_compute(sAh, sAl, sBh, sBl, warpM, warpN, lane, acc);
        __syncthreads();
    }

    // epilogue: bias + relu + split hi/lo
    int group = lane >> 2, tid4 = lane & 3;
#pragma unroll
    for (int mf = 0; mf < 2; mf++) {
#pragma unroll
        for (int half = 0; half < 2; half++) {
            int m = tm * TILE + warpM * 32 + mf * 16 + group + half * 8;
            if (m < cnt) {
                size_t hrow = (size_t)(base + m) * FFN;
#pragma unroll
                for (int nf = 0; nf < 8; nf++) {
                    int col = tn * TILE + warpN * 64 + nf * 8 + tid4 * 2;
                    float v0 = fmaxf(acc[mf][nf][half * 2 + 0] + b1[e * FFN + col],     0.f);
                    float v1 = fmaxf(acc[mf][nf][half * 2 + 1] + b1[e * FFN + col + 1], 0.f);
                    __nv_bfloat16 h0 = __float2bfloat16(v0), h1 = __float2bfloat16(v1);
                    *(__nv_bfloat162*)(g_hh + hrow + col) = __halves2bfloat162(h0, h1);
                    *(__nv_bfloat162*)(g_hl + hrow + col) =
                        __halves2bfloat162(__float2bfloat16(v0 - __bfloat162float(h0)),
                                           __float2bfloat16(v1 - __bfloat162float(h1)));
                }
            }
        }
    }
}

// ---------------------------------------------------------------------------
// GEMM2 (HMMA): out[tok[row]] += gate * (hidden[row] @ w2[e] + b2[e])
// ---------------------------------------------------------------------------
__global__ __launch_bounds__(256)
void gemm2_mma(const float* __restrict__ b2, float* __restrict__ out) {
    int e = blockIdx.z;
    int cnt = g_cnt[e];
    int tm = blockIdx.y;
    if (tm * TILE >= cnt) return;
    int tn = blockIdx.x;
    int base = g_off[e];

    __shared__ Smem sm;
    int tid = threadIdx.x, wid = tid >> 5, lane = tid & 31;
    int warpM = wid & 3, warpN = wid >> 2;

    uint32_t sAh = smem_u32(sm.Ah), sAl = smem_u32(sm.Al);
    uint32_t sBh = smem_u32(sm.Bh), sBl = smem_u32(sm.Bl);

    const __nv_bfloat16* Bhg = g_w2h + (size_t)e * DMODEL * FFN + (size_t)tn * TILE * FFN;
    const __nv_bfloat16* Blg = g_w2l + (size_t)e * DMODEL * FFN + (size_t)tn * TILE * FFN;

    float acc[2][8][4];
#pragma unroll
    for (int i = 0; i < 2; i++)
#pragma unroll
        for (int j = 0; j < 8; j++)
#pragma unroll
            for (int c = 0; c < 4; c++) acc[i][j][c] = 0.f;

    for (int ch = 0; ch < FFN / BK; ch++) {
        int koff = ch * BK;
#pragma unroll
        for (int u = tid; u < 512; u += 256) {
            int r = u >> 2, j = u & 3;
            uint32_t so = r * PAD + j * 8;
            int m = tm * TILE + r;
            if (m >= cnt) m = cnt - 1;
            size_t ao = (size_t)(base + m) * FFN + koff + j * 8;
            *(uint4*)(sm.Ah + so) = *(const uint4*)(g_hh + ao);
            *(uint4*)(sm.Al + so) = *(const uint4*)(g_hl + ao);
            size_t bo = (size_t)r * FFN + koff + j * 8;
            *(uint4*)(sm.Bh + so) = *(const uint4*)(Bhg + bo);
            *(uint4*)(sm.Bl + so) = *(const uint4*)(Blg + bo);
        }
        __syncthreads();
        gemm_chunk_compute(sAh, sAl, sBh, sBl, warpM, warpN, lane, acc);
        __syncthreads();
    }

    int group = lane >> 2, tid4 = lane & 3;
#pragma unroll
    for (int mf = 0; mf < 2; mf++) {
#pragma unroll
        for (int half = 0; half < 2; half++) {
            int m = tm * TILE + warpM * 32 + mf * 16 + group + half * 8;
            if (m < cnt) {
                int   token = g_tok[base + m];
                float gate  = g_gate[base + m];
                float* orow = out + (size_t)token * DMODEL;
#pragma unroll
                for (int nf = 0; nf < 8; nf++) {
                    int col = tn * TILE + warpN * 64 + nf * 8 + tid4 * 2;
                    float v0 = (acc[mf][nf][half * 2 + 0] + b2[e * DMODEL + col])     * gate;
                    float v1 = (acc[mf][nf][half * 2 + 1] + b2[e * DMODEL + col + 1]) * gate;
                    atomicAdd(&orow[col],     v0);
                    atomicAdd(&orow[col + 1], v1);
                }
            }
        }
    }
}

// ---------------------------------------------------------------------------
extern "C" void kernel_launch(void* const* d_in, const int* in_sizes, int n_in,
                              void* d_out, int out_size) {
    const float* x   = (const float*)d_in[0];
    const float* rw  = (const float*)d_in[1];
    const float* rb  = (const float*)d_in[2];
    const float* w1  = (const float*)d_in[3];
    const float* b1  = (const float*)d_in[4];
    const float* w2  = (const float*)d_in[5];
    const float* b2  = (const float*)d_in[6];
    float* out = (float*)d_out;

    zero_kernel<<<1024, 256>>>(out, NTOK * DMODEL);
    convert_x_kernel<<<1024, 256>>>(x);
    transconv_w1_kernel<<<dim3(FFN / 32, DMODEL / 32, NEXP), dim3(32, 8)>>>(w1);
    transconv_w2_kernel<<<dim3(DMODEL / 32, FFN / 32, NEXP), dim3(32, 8)>>>(w2);

    router_kernel<<<(NTOK * 32) / 256, 256>>>(x, rw, rb);
    offsets_kernel<<<1, 1>>>();
    scatter_kernel<<<NTOK / 256, 256>>>();

    gemm1_mma<<<dim3(FFN / TILE, NTOK / TILE, NEXP), 256>>>(b1);
    gemm2_mma<<<dim3(DMODEL / TILE, NTOK / TILE, NEXP), 256>>>(b2, out);
}

// round 7
// speedup vs baseline: 1.9846x; 1.2282x over previous
#include <cuda_runtime.h>
#include <cuda_bf16.h>
#include <cstdint>

// Problem constants
#define DMODEL 512
#define FFN    2048
#define NEXP   8
#define TOPK   2
#define NTOK   8192
#define NROWS  (NTOK * TOPK)
#define TILE   128
#define BK     32          // bf16 K elems per smem chunk
#define PAD    40          // smem row stride in bf16 (80 B, conflict-free, 16B-aligned)

#define ABYTES (TILE * PAD * 2)      // 10240 B per array
#define STAGE  (4 * ABYTES)          // Ah|Al|Bh|Bl per stage = 40960 B
#define DSMEM  (2 * STAGE)           // 81920 B dynamic smem

// ---------------------------------------------------------------------------
// Device scratch (static). ~208 MB total.
// ---------------------------------------------------------------------------
__device__ __nv_bfloat16 g_xh[(size_t)NTOK * DMODEL];
__device__ __nv_bfloat16 g_xl[(size_t)NTOK * DMODEL];
__device__ __nv_bfloat16 g_w1h[(size_t)NEXP * FFN * DMODEL];   // [E][F][D]
__device__ __nv_bfloat16 g_w1l[(size_t)NEXP * FFN * DMODEL];
__device__ __nv_bfloat16 g_w2h[(size_t)NEXP * DMODEL * FFN];   // [E][D][F]
__device__ __nv_bfloat16 g_w2l[(size_t)NEXP * DMODEL * FFN];
__device__ __nv_bfloat16 g_hh[(size_t)NROWS * FFN];
__device__ __nv_bfloat16 g_hl[(size_t)NROWS * FFN];
__device__ int   g_cnt[NEXP];
__device__ int   g_off[NEXP];
__device__ int   g_cursor[NEXP];
__device__ int   g_tok[NROWS];
__device__ float g_gate[NROWS];
__device__ int   g_pick_e[NROWS];
__device__ float g_pick_w[NROWS];

// ---------------------------------------------------------------------------
__device__ __forceinline__ uint32_t smem_u32(const void* p) {
    uint32_t a;
    asm("{ .reg .u64 t; cvta.to.shared.u64 t, %1; cvt.u32.u64 %0, t; }" : "=r"(a) : "l"(p));
    return a;
}

#define LDSM4(R0, R1, R2, R3, ADDR) \
    asm volatile("ldmatrix.sync.aligned.m8n8.x4.shared.b16 {%0,%1,%2,%3}, [%4];" \
                 : "=r"(R0), "=r"(R1), "=r"(R2), "=r"(R3) : "r"(ADDR))

#define MMA16816(C, A, B0, B1) \
    asm volatile("mma.sync.aligned.m16n8k16.row.col.f32.bf16.bf16.f32 " \
                 "{%0,%1,%2,%3}, {%4,%5,%6,%7}, {%8,%9}, {%0,%1,%2,%3};" \
                 : "+f"((C)[0]), "+f"((C)[1]), "+f"((C)[2]), "+f"((C)[3]) \
                 : "r"((A)[0]), "r"((A)[1]), "r"((A)[2]), "r"((A)[3]), "r"(B0), "r"(B1))

#define CPA16(DST, SRC) \
    asm volatile("cp.async.cg.shared.global [%0], [%1], 16;" :: "r"(DST), "l"(SRC))
#define CP_COMMIT() asm volatile("cp.async.commit_group;")
#define CP_WAIT1()  asm volatile("cp.async.wait_group 1;")

// ---------------------------------------------------------------------------
__global__ void zero_kernel(float* __restrict__ out, int n) {
    int i = blockIdx.x * blockDim.x + threadIdx.x;
    if (i < NEXP) { g_cnt[i] = 0; g_cursor[i] = 0; }
    float4* o4 = (float4*)out;
    int n4 = n >> 2;
    float4 z = make_float4(0.f, 0.f, 0.f, 0.f);
    for (int j = i; j < n4; j += gridDim.x * blockDim.x) o4[j] = z;
}

// x -> bf16 hi/lo (device globals referenced only from device code)
__global__ void convert_x_kernel(const float* __restrict__ x) {
    int tot = NTOK * DMODEL / 4;
    for (int i = blockIdx.x * blockDim.x + threadIdx.x; i < tot; i += gridDim.x * blockDim.x) {
        float4 v = ((const float4*)x)[i];
        __nv_bfloat16 h0 = __float2bfloat16(v.x), h1 = __float2bfloat16(v.y);
        __nv_bfloat16 h2 = __float2bfloat16(v.z), h3 = __float2bfloat16(v.w);
        __nv_bfloat162* ph = (__nv_bfloat162*)(g_xh + (size_t)i * 4);
        ph[0] = __halves2bfloat162(h0, h1);
        ph[1] = __halves2bfloat162(h2, h3);
        __nv_bfloat162* pl = (__nv_bfloat162*)(g_xl + (size_t)i * 4);
        pl[0] = __halves2bfloat162(__float2bfloat16(v.x - __bfloat162float(h0)),
                                   __float2bfloat16(v.y - __bfloat162float(h1)));
        pl[1] = __halves2bfloat162(__float2bfloat16(v.z - __bfloat162float(h2)),
                                   __float2bfloat16(v.w - __bfloat162float(h3)));
    }
}

__device__ __forceinline__ void transconv_body(const float* __restrict__ w,
                                               __nv_bfloat16* __restrict__ oh,
                                               __nv_bfloat16* __restrict__ ol,
                                               int K, int N) {
    __shared__ float t[32][33];
    int e = blockIdx.z;
    const float* we = w + (size_t)e * K * N;
    int n0 = blockIdx.x * 32, k0 = blockIdx.y * 32;
    int tx = threadIdx.x, ty = threadIdx.y;
    for (int i = ty; i < 32; i += 8)
        t[i][tx] = we[(size_t)(k0 + i) * N + n0 + tx];
    __syncthreads();
    size_t ob = (size_t)e * N * K;
    for (int i = ty; i < 32; i += 8) {
        float v = t[tx][i];
        __nv_bfloat16 h = __float2bfloat16(v);
        size_t o = ob + (size_t)(n0 + i) * K + k0 + tx;
        oh[o] = h;
        ol[o] = __float2bfloat16(v - __bfloat162float(h));
    }
}
__global__ void transconv_w1_kernel(const float* __restrict__ w1) {
    transconv_body(w1, g_w1h, g_w1l, DMODEL, FFN);
}
__global__ void transconv_w2_kernel(const float* __restrict__ w2) {
    transconv_body(w2, g_w2h, g_w2l, FFN, DMODEL);
}

// ---------------------------------------------------------------------------
// Router / offsets / scatter (validated)
// ---------------------------------------------------------------------------
__global__ void router_kernel(const float* __restrict__ x,
                              const float* __restrict__ rw,
                              const float* __restrict__ rb) {
    int warp = (blockIdx.x * blockDim.x + threadIdx.x) >> 5;
    int lane = threadIdx.x & 31;
    if (warp >= NTOK) return;
    const float* xr = x + (size_t)warp * DMODEL;
    float acc[NEXP];
#pragma unroll
    for (int e = 0; e < NEXP; e++) acc[e] = 0.0f;
    for (int d = lane; d < DMODEL; d += 32) {
        float xv = xr[d];
#pragma unroll
        for (int e = 0; e < NEXP; e++) acc[e] += xv * rw[d * NEXP + e];
    }
#pragma unroll
    for (int e = 0; e < NEXP; e++) {
#pragma unroll
        for (int o = 16; o > 0; o >>= 1) acc[e] += __shfl_xor_sync(0xffffffffu, acc[e], o);
    }
    if (lane == 0) {
        float l[NEXP];
#pragma unroll
        for (int e = 0; e < NEXP; e++) l[e] = acc[e] + rb[e];
        int i0 = 0;
#pragma unroll
        for (int e = 1; e < NEXP; e++) if (l[e] > l[i0]) i0 = e;
        int i1 = -1;
#pragma unroll
        for (int e = 0; e < NEXP; e++) {
            if (e == i0) continue;
            if (i1 < 0 || l[e] > l[i1]) i1 = e;
        }
        float z  = expf(l[i1] - l[i0]);
        float w0 = 1.0f / (1.0f + z);
        float w1 = z * w0;
        g_pick_e[warp * 2 + 0] = i0;  g_pick_w[warp * 2 + 0] = w0;
        g_pick_e[warp * 2 + 1] = i1;  g_pick_w[warp * 2 + 1] = w1;
        atomicAdd(&g_cnt[i0], 1);
        atomicAdd(&g_cnt[i1], 1);
    }
}

__global__ void offsets_kernel() {
    int s = 0;
#pragma unroll
    for (int e = 0; e < NEXP; e++) { g_off[e] = s; s += g_cnt[e]; }
}

__global__ void scatter_kernel() {
    int t = blockIdx.x * blockDim.x + threadIdx.x;
    if (t >= NTOK) return;
#pragma unroll
    for (int k = 0; k < TOPK; k++) {
        int e   = g_pick_e[t * 2 + k];
        int pos = atomicAdd(&g_cursor[e], 1);
        int row = g_off[e] + pos;
        g_tok[row]  = t;
        g_gate[row] = g_pick_w[t * 2 + k];
    }
}

// ---------------------------------------------------------------------------
// GEMM compute core on one smem stage (identical fragment math to R6-pass)
// ---------------------------------------------------------------------------
__device__ __forceinline__ void gemm_chunk_compute(
    uint32_t st, int warpM, int warpN, int lane, float acc[2][8][4]) {
    uint32_t sAh = st, sAl = st + ABYTES, sBh = st + 2 * ABYTES, sBl = st + 3 * ABYTES;
    int r16 = lane & 15;
    int c8  = (lane >> 4) * 8;
#pragma unroll
    for (int ks = 0; ks < 2; ks++) {
        int kb = ks * 16 + c8;
        uint32_t ah[2][4], al[2][4], bb[8][2];
#pragma unroll
        for (int mf = 0; mf < 2; mf++) {
            uint32_t off = ((warpM * 32 + mf * 16 + r16) * PAD + kb) * 2;
            LDSM4(ah[mf][0], ah[mf][1], ah[mf][2], ah[mf][3], sAh + off);
            LDSM4(al[mf][0], al[mf][1], al[mf][2], al[mf][3], sAl + off);
        }
#pragma unroll
        for (int nq = 0; nq < 4; nq++) {
            uint32_t off = ((warpN * 64 + nq * 16 + r16) * PAD + kb) * 2;
            uint32_t r0, r1, r2, r3;
            LDSM4(r0, r1, r2, r3, sBh + off);
            bb[2 * nq][0] = r0; bb[2 * nq][1] = r2;
            bb[2 * nq + 1][0] = r1; bb[2 * nq + 1][1] = r3;
        }
#pragma unroll
        for (int mf = 0; mf < 2; mf++)
#pragma unroll
            for (int nf = 0; nf < 8; nf++) {
                MMA16816(acc[mf][nf], ah[mf], bb[nf][0], bb[nf][1]);
                MMA16816(acc[mf][nf], al[mf], bb[nf][0], bb[nf][1]);
            }
#pragma unroll
        for (int nq = 0; nq < 4; nq++) {
            uint32_t off = ((warpN * 64 + nq * 16 + r16) * PAD + kb) * 2;
            uint32_t r0, r1, r2, r3;
            LDSM4(r0, r1, r2, r3, sBl + off);
            bb[2 * nq][0] = r0; bb[2 * nq][1] = r2;
            bb[2 * nq + 1][0] = r1; bb[2 * nq + 1][1] = r3;
        }
#pragma unroll
        for (int mf = 0; mf < 2; mf++)
#pragma unroll
            for (int nf = 0; nf < 8; nf++)
                MMA16816(acc[mf][nf], ah[mf], bb[nf][0], bb[nf][1]);
    }
}

// ---------------------------------------------------------------------------
// GEMM1 (HMMA + cp.async pipeline): hidden = relu(x[tok] @ w1[e] + b1[e])
// ---------------------------------------------------------------------------
__global__ __launch_bounds__(256)
void gemm1_mma(const float* __restrict__ b1) {
    int e = blockIdx.z;
    int cnt = g_cnt[e];
    int tm = blockIdx.y;
    if (tm * TILE >= cnt) return;
    int tn = blockIdx.x;
    int base = g_off[e];

    extern __shared__ __align__(16) char dyn[];
    __shared__ int s_tok[TILE];
    int tid = threadIdx.x, wid = tid >> 5, lane = tid & 31;
    int warpM = wid & 3, warpN = wid >> 2;

    if (tid < TILE) {
        int m = tm * TILE + tid;
        if (m >= cnt) m = cnt - 1;
        s_tok[tid] = g_tok[base + m];
    }
    __syncthreads();

    uint32_t sb = smem_u32(dyn);
    const __nv_bfloat16* Bhg = g_w1h + (size_t)e * FFN * DMODEL + (size_t)tn * TILE * DMODEL;
    const __nv_bfloat16* Blg = g_w1l + (size_t)e * FFN * DMODEL + (size_t)tn * TILE * DMODEL;

    // per-thread copy slots: 2 (r,j) pairs, 4 arrays each
    int r0c = tid >> 2,          j0 = tid & 3;
    int r1c = (tid + 256) >> 2,  j1 = (tid + 256) & 3;

    auto load_chunk = [&](int ch, int s) {
        uint32_t st = sb + s * STAGE;
        int koff = ch * BK;
        {
            uint32_t so = (r0c * PAD + j0 * 8) * 2;
            size_t ao = (size_t)s_tok[r0c] * DMODEL + koff + j0 * 8;
            size_t bo = (size_t)r0c * DMODEL + koff + j0 * 8;
            CPA16(st + so,              g_xh + ao);
            CPA16(st + ABYTES + so,     g_xl + ao);
            CPA16(st + 2 * ABYTES + so, Bhg + bo);
            CPA16(st + 3 * ABYTES + so, Blg + bo);
        }
        {
            uint32_t so = (r1c * PAD + j1 * 8) * 2;
            size_t ao = (size_t)s_tok[r1c] * DMODEL + koff + j1 * 8;
            size_t bo = (size_t)r1c * DMODEL + koff + j1 * 8;
            CPA16(st + so,              g_xh + ao);
            CPA16(st + ABYTES + so,     g_xl + ao);
            CPA16(st + 2 * ABYTES + so, Bhg + bo);
            CPA16(st + 3 * ABYTES + so, Blg + bo);
        }
    };

    float acc[2][8][4];
#pragma unroll
    for (int i = 0; i < 2; i++)
#pragma unroll
        for (int j = 0; j < 8; j++)
#pragma unroll
            for (int c = 0; c < 4; c++) acc[i][j][c] = 0.f;

    const int NCH = DMODEL / BK;   // 16
    load_chunk(0, 0);
    CP_COMMIT();
    for (int c = 0; c < NCH; c++) {
        if (c + 1 < NCH) load_chunk(c + 1, (c + 1) & 1);
        CP_COMMIT();
        CP_WAIT1();
        __syncthreads();
        gemm_chunk_compute(sb + (c & 1) * STAGE, warpM, warpN, lane, acc);
        __syncthreads();
    }

    // epilogue: bias + relu + split hi/lo
    int group = lane >> 2, tid4 = lane & 3;
#pragma unroll
    for (int mf = 0; mf < 2; mf++) {
#pragma unroll
        for (int half = 0; half < 2; half++) {
            int m = tm * TILE + warpM * 32 + mf * 16 + group + half * 8;
            if (m < cnt) {
                size_t hrow = (size_t)(base + m) * FFN;
#pragma unroll
                for (int nf = 0; nf < 8; nf++) {
                    int col = tn * TILE + warpN * 64 + nf * 8 + tid4 * 2;
                    float v0 = fmaxf(acc[mf][nf][half * 2 + 0] + b1[e * FFN + col],     0.f);
                    float v1 = fmaxf(acc[mf][nf][half * 2 + 1] + b1[e * FFN + col + 1], 0.f);
                    __nv_bfloat16 h0 = __float2bfloat16(v0), h1 = __float2bfloat16(v1);
                    *(__nv_bfloat162*)(g_hh + hrow + col) = __halves2bfloat162(h0, h1);
                    *(__nv_bfloat162*)(g_hl + hrow + col) =
                        __halves2bfloat162(__float2bfloat16(v0 - __bfloat162float(h0)),
                                           __float2bfloat16(v1 - __bfloat162float(h1)));
                }
            }
        }
    }
}

// ---------------------------------------------------------------------------
// GEMM2 (HMMA + cp.async pipeline): out += gate * (hidden @ w2[e] + b2[e])
// ---------------------------------------------------------------------------
__global__ __launch_bounds__(256)
void gemm2_mma(const float* __restrict__ b2, float* __restrict__ out) {
    int e = blockIdx.z;
    int cnt = g_cnt[e];
    int tm = blockIdx.y;
    if (tm * TILE >= cnt) return;
    int tn = blockIdx.x;
    int base = g_off[e];

    extern __shared__ __align__(16) char dyn[];
    __shared__ int s_row[TILE];
    int tid = threadIdx.x, wid = tid >> 5, lane = tid & 31;
    int warpM = wid & 3, warpN = wid >> 2;

    if (tid < TILE) {
        int m = tm * TILE + tid;
        if (m >= cnt) m = cnt - 1;
        s_row[tid] = base + m;
    }
    __syncthreads();

    uint32_t sb = smem_u32(dyn);
    const __nv_bfloat16* Bhg = g_w2h + (size_t)e * DMODEL * FFN + (size_t)tn * TILE * FFN;
    const __nv_bfloat16* Blg = g_w2l + (size_t)e * DMODEL * FFN + (size_t)tn * TILE * FFN;

    int r0c = tid >> 2,          j0 = tid & 3;
    int r1c = (tid + 256) >> 2,  j1 = (tid + 256) & 3;

    auto load_chunk = [&](int ch, int s) {
        uint32_t st = sb + s * STAGE;
        int koff = ch * BK;
        {
            uint32_t so = (r0c * PAD + j0 * 8) * 2;
            size_t ao = (size_t)s_row[r0c] * FFN + koff + j0 * 8;
            size_t bo = (size_t)r0c * FFN + koff + j0 * 8;
            CPA16(st + so,              g_hh + ao);
            CPA16(st + ABYTES + so,     g_hl + ao);
            CPA16(st + 2 * ABYTES + so, Bhg + bo);
            CPA16(st + 3 * ABYTES + so, Blg + bo);
        }
        {
            uint32_t so = (r1c * PAD + j1 * 8) * 2;
            size_t ao = (size_t)s_row[r1c] * FFN + koff + j1 * 8;
            size_t bo = (size_t)r1c * FFN + koff + j1 * 8;
            CPA16(st + so,              g_hh + ao);
            CPA16(st + ABYTES + so,     g_hl + ao);
            CPA16(st + 2 * ABYTES + so, Bhg + bo);
            CPA16(st + 3 * ABYTES + so, Blg + bo);
        }
    };

    float acc[2][8][4];
#pragma unroll
    for (int i = 0; i < 2; i++)
#pragma unroll
        for (int j = 0; j < 8; j++)
#pragma unroll
            for (int c = 0; c < 4; c++) acc[i][j][c] = 0.f;

    const int NCH = FFN / BK;   // 64
    load_chunk(0, 0);
    CP_COMMIT();
    for (int c = 0; c < NCH; c++) {
        if (c + 1 < NCH) load_chunk(c + 1, (c + 1) & 1);
        CP_COMMIT();
        CP_WAIT1();
        __syncthreads();
        gemm_chunk_compute(sb + (c & 1) * STAGE, warpM, warpN, lane, acc);
        __syncthreads();
    }

    int group = lane >> 2, tid4 = lane & 3;
#pragma unroll
    for (int mf = 0; mf < 2; mf++) {
#pragma unroll
        for (int half = 0; half < 2; half++) {
            int m = tm * TILE + warpM * 32 + mf * 16 + group + half * 8;
            if (m < cnt) {
                int   token = g_tok[base + m];
                float gate  = g_gate[base + m];
                float* orow = out + (size_t)token * DMODEL;
#pragma unroll
                for (int nf = 0; nf < 8; nf++) {
                    int col = tn * TILE + warpN * 64 + nf * 8 + tid4 * 2;
                    float v0 = (acc[mf][nf][half * 2 + 0] + b2[e * DMODEL + col])     * gate;
                    float v1 = (acc[mf][nf][half * 2 + 1] + b2[e * DMODEL + col + 1]) * gate;
                    atomicAdd(&orow[col],     v0);
                    atomicAdd(&orow[col + 1], v1);
                }
            }
        }
    }
}

// ---------------------------------------------------------------------------
extern "C" void kernel_launch(void* const* d_in, const int* in_sizes, int n_in,
                              void* d_out, int out_size) {
    const float* x   = (const float*)d_in[0];
    const float* rw  = (const float*)d_in[1];
    const float* rb  = (const float*)d_in[2];
    const float* w1  = (const float*)d_in[3];
    const float* b1  = (const float*)d_in[4];
    const float* w2  = (const float*)d_in[5];
    const float* b2  = (const float*)d_in[6];
    float* out = (float*)d_out;

    static bool attr_set = false;
    if (!attr_set) {
        cudaFuncSetAttribute(gemm1_mma, cudaFuncAttributeMaxDynamicSharedMemorySize, DSMEM);
        cudaFuncSetAttribute(gemm2_mma, cudaFuncAttributeMaxDynamicSharedMemorySize, DSMEM);
        attr_set = true;
    }

    zero_kernel<<<1024, 256>>>(out, NTOK * DMODEL);
    convert_x_kernel<<<1024, 256>>>(x);
    transconv_w1_kernel<<<dim3(FFN / 32, DMODEL / 32, NEXP), dim3(32, 8)>>>(w1);
    transconv_w2_kernel<<<dim3(DMODEL / 32, FFN / 32, NEXP), dim3(32, 8)>>>(w2);

    router_kernel<<<(NTOK * 32) / 256, 256>>>(x, rw, rb);
    offsets_kernel<<<1, 1>>>();
    scatter_kernel<<<NTOK / 256, 256>>>();

    gemm1_mma<<<dim3(FFN / TILE, NTOK / TILE, NEXP), 256, DSMEM>>>(b1);
    gemm2_mma<<<dim3(DMODEL / TILE, NTOK / TILE, NEXP), 256, DSMEM>>>(b2, out);
}

// round 8
// speedup vs baseline: 3.0844x; 1.5542x over previous
#include <cuda_runtime.h>
#include <cuda_fp16.h>
#include <cstdint>

// Problem constants
#define DMODEL 512
#define FFN    2048
#define NEXP   8
#define TOPK   2
#define NTOK   8192
#define NROWS  (NTOK * TOPK)
#define TILE   128
#define BK     32          // fp16 K elems per smem chunk
#define PAD    40          // smem row stride in fp16 (80 B, conflict-free, 16B-aligned)

#define ABYTES (TILE * PAD * 2)      // 10240 B per array
#define STAGE  (3 * ABYTES)          // Ah|Al|Bh per stage = 30720 B
#define DSMEM  (2 * STAGE)           // 61440 B dynamic smem

// ---------------------------------------------------------------------------
// Device scratch (static).
// ---------------------------------------------------------------------------
__device__ __half g_xh[(size_t)NTOK * DMODEL];
__device__ __half g_xl[(size_t)NTOK * DMODEL];
__device__ __half g_w1h[(size_t)NEXP * FFN * DMODEL];   // [E][F][D] transposed, fp16
__device__ __half g_w2h[(size_t)NEXP * DMODEL * FFN];   // [E][D][F] transposed, fp16
__device__ __half g_hh[(size_t)NROWS * FFN];
__device__ __half g_hl[(size_t)NROWS * FFN];
__device__ int   g_cnt[NEXP];
__device__ int   g_off[NEXP];
__device__ int   g_cursor[NEXP];
__device__ int   g_tok[NROWS];
__device__ float g_gate[NROWS];
__device__ int   g_pick_e[NROWS];
__device__ float g_pick_w[NROWS];

// ---------------------------------------------------------------------------
__device__ __forceinline__ uint32_t smem_u32(const void* p) {
    uint32_t a;
    asm("{ .reg .u64 t; cvta.to.shared.u64 t, %1; cvt.u32.u64 %0, t; }" : "=r"(a) : "l"(p));
    return a;
}

#define LDSM4(R0, R1, R2, R3, ADDR) \
    asm volatile("ldmatrix.sync.aligned.m8n8.x4.shared.b16 {%0,%1,%2,%3}, [%4];" \
                 : "=r"(R0), "=r"(R1), "=r"(R2), "=r"(R3) : "r"(ADDR))

#define MMA16816(C, A, B0, B1) \
    asm volatile("mma.sync.aligned.m16n8k16.row.col.f32.f16.f16.f32 " \
                 "{%0,%1,%2,%3}, {%4,%5,%6,%7}, {%8,%9}, {%0,%1,%2,%3};" \
                 : "+f"((C)[0]), "+f"((C)[1]), "+f"((C)[2]), "+f"((C)[3]) \
                 : "r"((A)[0]), "r"((A)[1]), "r"((A)[2]), "r"((A)[3]), "r"(B0), "r"(B1))

#define CPA16(DST, SRC) \
    asm volatile("cp.async.cg.shared.global [%0], [%1], 16;" :: "r"(DST), "l"(SRC))
#define CP_COMMIT() asm volatile("cp.async.commit_group;")
#define CP_WAIT1()  asm volatile("cp.async.wait_group 1;")

// ---------------------------------------------------------------------------
__global__ void zero_kernel(float* __restrict__ out, int n) {
    int i = blockIdx.x * blockDim.x + threadIdx.x;
    if (i < NEXP) { g_cnt[i] = 0; g_cursor[i] = 0; }
    float4* o4 = (float4*)out;
    int n4 = n >> 2;
    float4 z = make_float4(0.f, 0.f, 0.f, 0.f);
    for (int j = i; j < n4; j += gridDim.x * blockDim.x) o4[j] = z;
}

// x -> fp16 hi + fp16 lo (captures ~22 mantissa bits)
__global__ void convert_x_kernel(const float* __restrict__ x) {
    int tot = NTOK * DMODEL / 4;
    for (int i = blockIdx.x * blockDim.x + threadIdx.x; i < tot; i += gridDim.x * blockDim.x) {
        float4 v = ((const float4*)x)[i];
        __half h0 = __float2half_rn(v.x), h1 = __float2half_rn(v.y);
        __half h2 = __float2half_rn(v.z), h3 = __float2half_rn(v.w);
        __half2* ph = (__half2*)(g_xh + (size_t)i * 4);
        ph[0] = __halves2half2(h0, h1);
        ph[1] = __halves2half2(h2, h3);
        __half2* pl = (__half2*)(g_xl + (size_t)i * 4);
        pl[0] = __halves2half2(__float2half_rn(v.x - __half2float(h0)),
                               __float2half_rn(v.y - __half2float(h1)));
        pl[1] = __halves2half2(__float2half_rn(v.z - __half2float(h2)),
                               __float2half_rn(v.w - __half2float(h3)));
    }
}

// Transpose-convert: w [E][K][N] fp32 -> oh [E][N][K] fp16 (hi only)
__device__ __forceinline__ void transconv_body(const float* __restrict__ w,
                                               __half* __restrict__ oh,
                                               int K, int N) {
    __shared__ float t[32][33];
    int e = blockIdx.z;
    const float* we = w + (size_t)e * K * N;
    int n0 = blockIdx.x * 32, k0 = blockIdx.y * 32;
    int tx = threadIdx.x, ty = threadIdx.y;
    for (int i = ty; i < 32; i += 8)
        t[i][tx] = we[(size_t)(k0 + i) * N + n0 + tx];
    __syncthreads();
    size_t ob = (size_t)e * N * K;
    for (int i = ty; i < 32; i += 8)
        oh[ob + (size_t)(n0 + i) * K + k0 + tx] = __float2half_rn(t[tx][i]);
}
__global__ void transconv_w1_kernel(const float* __restrict__ w1) {
    transconv_body(w1, g_w1h, DMODEL, FFN);
}
__global__ void transconv_w2_kernel(const float* __restrict__ w2) {
    transconv_body(w2, g_w2h, FFN, DMODEL);
}

// ---------------------------------------------------------------------------
// Router / offsets / scatter (validated)
// ---------------------------------------------------------------------------
__global__ void router_kernel(const float* __restrict__ x,
                              const float* __restrict__ rw,
                              const float* __restrict__ rb) {
    int warp = (blockIdx.x * blockDim.x + threadIdx.x) >> 5;
    int lane = threadIdx.x & 31;
    if (warp >= NTOK) return;
    const float* xr = x + (size_t)warp * DMODEL;
    float acc[NEXP];
#pragma unroll
    for (int e = 0; e < NEXP; e++) acc[e] = 0.0f;
    for (int d = lane; d < DMODEL; d += 32) {
        float xv = xr[d];
#pragma unroll
        for (int e = 0; e < NEXP; e++) acc[e] += xv * rw[d * NEXP + e];
    }
#pragma unroll
    for (int e = 0; e < NEXP; e++) {
#pragma unroll
        for (int o = 16; o > 0; o >>= 1) acc[e] += __shfl_xor_sync(0xffffffffu, acc[e], o);
    }
    if (lane == 0) {
        float l[NEXP];
#pragma unroll
        for (int e = 0; e < NEXP; e++) l[e] = acc[e] + rb[e];
        int i0 = 0;
#pragma unroll
        for (int e = 1; e < NEXP; e++) if (l[e] > l[i0]) i0 = e;
        int i1 = -1;
#pragma unroll
        for (int e = 0; e < NEXP; e++) {
            if (e == i0) continue;
            if (i1 < 0 || l[e] > l[i1]) i1 = e;
        }
        float z  = expf(l[i1] - l[i0]);
        float w0 = 1.0f / (1.0f + z);
        float w1 = z * w0;
        g_pick_e[warp * 2 + 0] = i0;  g_pick_w[warp * 2 + 0] = w0;
        g_pick_e[warp * 2 + 1] = i1;  g_pick_w[warp * 2 + 1] = w1;
        atomicAdd(&g_cnt[i0], 1);
        atomicAdd(&g_cnt[i1], 1);
    }
}

__global__ void offsets_kernel() {
    int s = 0;
#pragma unroll
    for (int e = 0; e < NEXP; e++) { g_off[e] = s; s += g_cnt[e]; }
}

__global__ void scatter_kernel() {
    int t = blockIdx.x * blockDim.x + threadIdx.x;
    if (t >= NTOK) return;
#pragma unroll
    for (int k = 0; k < TOPK; k++) {
        int e   = g_pick_e[t * 2 + k];
        int pos = atomicAdd(&g_cursor[e], 1);
        int row = g_off[e] + pos;
        g_tok[row]  = t;
        g_gate[row] = g_pick_w[t * 2 + k];
    }
}

// ---------------------------------------------------------------------------
// GEMM compute core: 2-pass fp16 (Ah·Bh + Al·Bh), fp32 accum
// ---------------------------------------------------------------------------
__device__ __forceinline__ void gemm_chunk_compute(
    uint32_t st, int warpM, int warpN, int lane, float acc[2][8][4]) {
    uint32_t sAh = st, sAl = st + ABYTES, sBh = st + 2 * ABYTES;
    int r16 = lane & 15;
    int c8  = (lane >> 4) * 8;
#pragma unroll
    for (int ks = 0; ks < 2; ks++) {
        int kb = ks * 16 + c8;
        uint32_t ah[2][4], al[2][4], bb[8][2];
#pragma unroll
        for (int mf = 0; mf < 2; mf++) {
            uint32_t off = ((warpM * 32 + mf * 16 + r16) * PAD + kb) * 2;
            LDSM4(ah[mf][0], ah[mf][1], ah[mf][2], ah[mf][3], sAh + off);
            LDSM4(al[mf][0], al[mf][1], al[mf][2], al[mf][3], sAl + off);
        }
#pragma unroll
        for (int nq = 0; nq < 4; nq++) {
            uint32_t off = ((warpN * 64 + nq * 16 + r16) * PAD + kb) * 2;
            uint32_t r0, r1, r2, r3;
            LDSM4(r0, r1, r2, r3, sBh + off);
            bb[2 * nq][0] = r0; bb[2 * nq][1] = r2;
            bb[2 * nq + 1][0] = r1; bb[2 * nq + 1][1] = r3;
        }
#pragma unroll
        for (int mf = 0; mf < 2; mf++)
#pragma unroll
            for (int nf = 0; nf < 8; nf++) {
                MMA16816(acc[mf][nf], ah[mf], bb[nf][0], bb[nf][1]);
                MMA16816(acc[mf][nf], al[mf], bb[nf][0], bb[nf][1]);
            }
    }
}

// ---------------------------------------------------------------------------
// GEMM1 (fp16 HMMA + cp.async): hidden = relu(x[tok] @ w1[e] + b1[e]); emit fp16 hi/lo
// ---------------------------------------------------------------------------
__global__ __launch_bounds__(256)
void gemm1_mma(const float* __restrict__ b1) {
    int e = blockIdx.z;
    int cnt = g_cnt[e];
    int tm = blockIdx.y;
    if (tm * TILE >= cnt) return;
    int tn = blockIdx.x;
    int base = g_off[e];

    extern __shared__ __align__(16) char dyn[];
    __shared__ int s_tok[TILE];
    int tid = threadIdx.x, wid = tid >> 5, lane = tid & 31;
    int warpM = wid & 3, warpN = wid >> 2;

    if (tid < TILE) {
        int m = tm * TILE + tid;
        if (m >= cnt) m = cnt - 1;
        s_tok[tid] = g_tok[base + m];
    }
    __syncthreads();

    uint32_t sb = smem_u32(dyn);
    const __half* Bhg = g_w1h + (size_t)e * FFN * DMODEL + (size_t)tn * TILE * DMODEL;

    int r0c = tid >> 2,          j0 = tid & 3;
    int r1c = (tid + 256) >> 2,  j1 = (tid + 256) & 3;

    auto load_chunk = [&](int ch, int s) {
        uint32_t st = sb + s * STAGE;
        int koff = ch * BK;
        {
            uint32_t so = (r0c * PAD + j0 * 8) * 2;
            size_t ao = (size_t)s_tok[r0c] * DMODEL + koff + j0 * 8;
            size_t bo = (size_t)r0c * DMODEL + koff + j0 * 8;
            CPA16(st + so,              g_xh + ao);
            CPA16(st + ABYTES + so,     g_xl + ao);
            CPA16(st + 2 * ABYTES + so, Bhg + bo);
        }
        {
            uint32_t so = (r1c * PAD + j1 * 8) * 2;
            size_t ao = (size_t)s_tok[r1c] * DMODEL + koff + j1 * 8;
            size_t bo = (size_t)r1c * DMODEL + koff + j1 * 8;
            CPA16(st + so,              g_xh + ao);
            CPA16(st + ABYTES + so,     g_xl + ao);
            CPA16(st + 2 * ABYTES + so, Bhg + bo);
        }
    };

    float acc[2][8][4];
#pragma unroll
    for (int i = 0; i < 2; i++)
#pragma unroll
        for (int j = 0; j < 8; j++)
#pragma unroll
            for (int c = 0; c < 4; c++) acc[i][j][c] = 0.f;

    const int NCH = DMODEL / BK;   // 16
    load_chunk(0, 0);
    CP_COMMIT();
    for (int c = 0; c < NCH; c++) {
        if (c + 1 < NCH) load_chunk(c + 1, (c + 1) & 1);
        CP_COMMIT();
        CP_WAIT1();
        __syncthreads();
        gemm_chunk_compute(sb + (c & 1) * STAGE, warpM, warpN, lane, acc);
        __syncthreads();
    }

    // epilogue: bias + relu + split fp16 hi/lo
    int group = lane >> 2, tid4 = lane & 3;
#pragma unroll
    for (int mf = 0; mf < 2; mf++) {
#pragma unroll
        for (int half = 0; half < 2; half++) {
            int m = tm * TILE + warpM * 32 + mf * 16 + group + half * 8;
            if (m < cnt) {
                size_t hrow = (size_t)(base + m) * FFN;
#pragma unroll
                for (int nf = 0; nf < 8; nf++) {
                    int col = tn * TILE + warpN * 64 + nf * 8 + tid4 * 2;
                    float v0 = fmaxf(acc[mf][nf][half * 2 + 0] + b1[e * FFN + col],     0.f);
                    float v1 = fmaxf(acc[mf][nf][half * 2 + 1] + b1[e * FFN + col + 1], 0.f);
                    __half h0 = __float2half_rn(v0), h1 = __float2half_rn(v1);
                    *(__half2*)(g_hh + hrow + col) = __halves2half2(h0, h1);
                    *(__half2*)(g_hl + hrow + col) =
                        __halves2half2(__float2half_rn(v0 - __half2float(h0)),
                                       __float2half_rn(v1 - __half2float(h1)));
                }
            }
        }
    }
}

// ---------------------------------------------------------------------------
// GEMM2 (fp16 HMMA + cp.async): out += gate * (hidden @ w2[e] + b2[e])
// ---------------------------------------------------------------------------
__global__ __launch_bounds__(256)
void gemm2_mma(const float* __restrict__ b2, float* __restrict__ out) {
    int e = blockIdx.z;
    int cnt = g_cnt[e];
    int tm = blockIdx.y;
    if (tm * TILE >= cnt) return;
    int tn = blockIdx.x;
    int base = g_off[e];

    extern __shared__ __align__(16) char dyn[];
    __shared__ int s_row[TILE];
    int tid = threadIdx.x, wid = tid >> 5, lane = tid & 31;
    int warpM = wid & 3, warpN = wid >> 2;

    if (tid < TILE) {
        int m = tm * TILE + tid;
        if (m >= cnt) m = cnt - 1;
        s_row[tid] = base + m;
    }
    __syncthreads();

    uint32_t sb = smem_u32(dyn);
    const __half* Bhg = g_w2h + (size_t)e * DMODEL * FFN + (size_t)tn * TILE * FFN;

    int r0c = tid >> 2,          j0 = tid & 3;
    int r1c = (tid + 256) >> 2,  j1 = (tid + 256) & 3;

    auto load_chunk = [&](int ch, int s) {
        uint32_t st = sb + s * STAGE;
        int koff = ch * BK;
        {
            uint32_t so = (r0c * PAD + j0 * 8) * 2;
            size_t ao = (size_t)s_row[r0c] * FFN + koff + j0 * 8;
            size_t bo = (size_t)r0c * FFN + koff + j0 * 8;
            CPA16(st + so,              g_hh + ao);
            CPA16(st + ABYTES + so,     g_hl + ao);
            CPA16(st + 2 * ABYTES + so, Bhg + bo);
        }
        {
            uint32_t so = (r1c * PAD + j1 * 8) * 2;
            size_t ao = (size_t)s_row[r1c] * FFN + koff + j1 * 8;
            size_t bo = (size_t)r1c * FFN + koff + j1 * 8;
            CPA16(st + so,              g_hh + ao);
            CPA16(st + ABYTES + so,     g_hl + ao);
            CPA16(st + 2 * ABYTES + so, Bhg + bo);
        }
    };

    float acc[2][8][4];
#pragma unroll
    for (int i = 0; i < 2; i++)
#pragma unroll
        for (int j = 0; j < 8; j++)
#pragma unroll
            for (int c = 0; c < 4; c++) acc[i][j][c] = 0.f;

    const int NCH = FFN / BK;   // 64
    load_chunk(0, 0);
    CP_COMMIT();
    for (int c = 0; c < NCH; c++) {
        if (c + 1 < NCH) load_chunk(c + 1, (c + 1) & 1);
        CP_COMMIT();
        CP_WAIT1();
        __syncthreads();
        gemm_chunk_compute(sb + (c & 1) * STAGE, warpM, warpN, lane, acc);
        __syncthreads();
    }

    int group = lane >> 2, tid4 = lane & 3;
#pragma unroll
    for (int mf = 0; mf < 2; mf++) {
#pragma unroll
        for (int half = 0; half < 2; half++) {
            int m = tm * TILE + warpM * 32 + mf * 16 + group + half * 8;
            if (m < cnt) {
                int   token = g_tok[base + m];
                float gate  = g_gate[base + m];
                float* orow = out + (size_t)token * DMODEL;
#pragma unroll
                for (int nf = 0; nf < 8; nf++) {
                    int col = tn * TILE + warpN * 64 + nf * 8 + tid4 * 2;
                    float v0 = (acc[mf][nf][half * 2 + 0] + b2[e * DMODEL + col])     * gate;
                    float v1 = (acc[mf][nf][half * 2 + 1] + b2[e * DMODEL + col + 1]) * gate;
                    atomicAdd(&orow[col],     v0);
                    atomicAdd(&orow[col + 1], v1);
                }
            }
        }
    }
}

// ---------------------------------------------------------------------------
extern "C" void kernel_launch(void* const* d_in, const int* in_sizes, int n_in,
                              void* d_out, int out_size) {
    const float* x   = (const float*)d_in[0];
    const float* rw  = (const float*)d_in[1];
    const float* rb  = (const float*)d_in[2];
    const float* w1  = (const float*)d_in[3];
    const float* b1  = (const float*)d_in[4];
    const float* w2  = (const float*)d_in[5];
    const float* b2  = (const float*)d_in[6];
    float* out = (float*)d_out;

    static bool attr_set = false;
    if (!attr_set) {
        cudaFuncSetAttribute(gemm1_mma, cudaFuncAttributeMaxDynamicSharedMemorySize, DSMEM);
        cudaFuncSetAttribute(gemm2_mma, cudaFuncAttributeMaxDynamicSharedMemorySize, DSMEM);
        attr_set = true;
    }

    zero_kernel<<<1024, 256>>>(out, NTOK * DMODEL);
    convert_x_kernel<<<1024, 256>>>(x);
    transconv_w1_kernel<<<dim3(FFN / 32, DMODEL / 32, NEXP), dim3(32, 8)>>>(w1);
    transconv_w2_kernel<<<dim3(DMODEL / 32, FFN / 32, NEXP), dim3(32, 8)>>>(w2);

    router_kernel<<<(NTOK * 32) / 256, 256>>>(x, rw, rb);
    offsets_kernel<<<1, 1>>>();
    scatter_kernel<<<NTOK / 256, 256>>>();

    gemm1_mma<<<dim3(FFN / TILE, NTOK / TILE, NEXP), 256, DSMEM>>>(b1);
    gemm2_mma<<<dim3(DMODEL / TILE, NTOK / TILE, NEXP), 256, DSMEM>>>(b2, out);
}

// round 9
// speedup vs baseline: 4.6160x; 1.4966x over previous
#include <cuda_runtime.h>
#include <cuda_fp16.h>
#include <cstdint>

// Problem constants
#define DMODEL 512
#define FFN    2048
#define NEXP   8
#define TOPK   2
#define NTOK   8192
#define NROWS  (NTOK * TOPK)
#define TILE   128
#define BK     32          // fp16 K elems per smem chunk
#define PAD    40          // smem row stride in fp16 (80 B, conflict-free, 16B-aligned)

#define ABYTES (TILE * PAD * 2)      // 10240 B per array
#define STAGE  (2 * ABYTES)          // A|B per stage = 20480 B
#define NSTG   3
#define DSMEM  (NSTG * STAGE)        // 61440 B dynamic smem

// ---------------------------------------------------------------------------
// Device scratch (static).
// ---------------------------------------------------------------------------
__device__ __half g_xh[(size_t)NTOK * DMODEL];
__device__ __half g_w1h[(size_t)NEXP * FFN * DMODEL];   // [E][F][D] transposed, fp16
__device__ __half g_w2h[(size_t)NEXP * DMODEL * FFN];   // [E][D][F] transposed, fp16
__device__ __half g_hh[(size_t)NROWS * FFN];
__device__ int   g_cnt[NEXP];
__device__ int   g_off[NEXP];
__device__ int   g_cursor[NEXP];
__device__ int   g_tok[NROWS];
__device__ float g_gate[NROWS];
__device__ int   g_pick_e[NROWS];
__device__ float g_pick_w[NROWS];

// ---------------------------------------------------------------------------
__device__ __forceinline__ uint32_t smem_u32(const void* p) {
    uint32_t a;
    asm("{ .reg .u64 t; cvta.to.shared.u64 t, %1; cvt.u32.u64 %0, t; }" : "=r"(a) : "l"(p));
    return a;
}

#define LDSM4(R0, R1, R2, R3, ADDR) \
    asm volatile("ldmatrix.sync.aligned.m8n8.x4.shared.b16 {%0,%1,%2,%3}, [%4];" \
                 : "=r"(R0), "=r"(R1), "=r"(R2), "=r"(R3) : "r"(ADDR))

#define MMA16816(C, A, B0, B1) \
    asm volatile("mma.sync.aligned.m16n8k16.row.col.f32.f16.f16.f32 " \
                 "{%0,%1,%2,%3}, {%4,%5,%6,%7}, {%8,%9}, {%0,%1,%2,%3};" \
                 : "+f"((C)[0]), "+f"((C)[1]), "+f"((C)[2]), "+f"((C)[3]) \
                 : "r"((A)[0]), "r"((A)[1]), "r"((A)[2]), "r"((A)[3]), "r"(B0), "r"(B1))

#define CPA16(DST, SRC) \
    asm volatile("cp.async.cg.shared.global [%0], [%1], 16;" :: "r"(DST), "l"(SRC))
#define CP_COMMIT() asm volatile("cp.async.commit_group;")
#define CP_WAIT2()  asm volatile("cp.async.wait_group 2;")

// ---------------------------------------------------------------------------
__global__ void zero_kernel(float* __restrict__ out, int n) {
    int i = blockIdx.x * blockDim.x + threadIdx.x;
    if (i < NEXP) { g_cnt[i] = 0; g_cursor[i] = 0; }
    float4* o4 = (float4*)out;
    int n4 = n >> 2;
    float4 z = make_float4(0.f, 0.f, 0.f, 0.f);
    for (int j = i; j < n4; j += gridDim.x * blockDim.x) o4[j] = z;
}

// x -> fp16 (hi only)
__global__ void convert_x_kernel(const float* __restrict__ x) {
    int tot = NTOK * DMODEL / 4;
    for (int i = blockIdx.x * blockDim.x + threadIdx.x; i < tot; i += gridDim.x * blockDim.x) {
        float4 v = ((const float4*)x)[i];
        __half2* ph = (__half2*)(g_xh + (size_t)i * 4);
        ph[0] = __halves2half2(__float2half_rn(v.x), __float2half_rn(v.y));
        ph[1] = __halves2half2(__float2half_rn(v.z), __float2half_rn(v.w));
    }
}

// Transpose-convert: w [E][K][N] fp32 -> oh [E][N][K] fp16
__device__ __forceinline__ void transconv_body(const float* __restrict__ w,
                                               __half* __restrict__ oh,
                                               int K, int N) {
    __shared__ float t[32][33];
    int e = blockIdx.z;
    const float* we = w + (size_t)e * K * N;
    int n0 = blockIdx.x * 32, k0 = blockIdx.y * 32;
    int tx = threadIdx.x, ty = threadIdx.y;
    for (int i = ty; i < 32; i += 8)
        t[i][tx] = we[(size_t)(k0 + i) * N + n0 + tx];
    __syncthreads();
    size_t ob = (size_t)e * N * K;
    for (int i = ty; i < 32; i += 8)
        oh[ob + (size_t)(n0 + i) * K + k0 + tx] = __float2half_rn(t[tx][i]);
}
__global__ void transconv_w1_kernel(const float* __restrict__ w1) {
    transconv_body(w1, g_w1h, DMODEL, FFN);
}
__global__ void transconv_w2_kernel(const float* __restrict__ w2) {
    transconv_body(w2, g_w2h, FFN, DMODEL);
}

// ---------------------------------------------------------------------------
// Router / offsets / scatter (validated)
// ---------------------------------------------------------------------------
__global__ void router_kernel(const float* __restrict__ x,
                              const float* __restrict__ rw,
                              const float* __restrict__ rb) {
    int warp = (blockIdx.x * blockDim.x + threadIdx.x) >> 5;
    int lane = threadIdx.x & 31;
    if (warp >= NTOK) return;
    const float* xr = x + (size_t)warp * DMODEL;
    float acc[NEXP];
#pragma unroll
    for (int e = 0; e < NEXP; e++) acc[e] = 0.0f;
    for (int d = lane; d < DMODEL; d += 32) {
        float xv = xr[d];
#pragma unroll
        for (int e = 0; e < NEXP; e++) acc[e] += xv * rw[d * NEXP + e];
    }
#pragma unroll
    for (int e = 0; e < NEXP; e++) {
#pragma unroll
        for (int o = 16; o > 0; o >>= 1) acc[e] += __shfl_xor_sync(0xffffffffu, acc[e], o);
    }
    if (lane == 0) {
        float l[NEXP];
#pragma unroll
        for (int e = 0; e < NEXP; e++) l[e] = acc[e] + rb[e];
        int i0 = 0;
#pragma unroll
        for (int e = 1; e < NEXP; e++) if (l[e] > l[i0]) i0 = e;
        int i1 = -1;
#pragma unroll
        for (int e = 0; e < NEXP; e++) {
            if (e == i0) continue;
            if (i1 < 0 || l[e] > l[i1]) i1 = e;
        }
        float z  = expf(l[i1] - l[i0]);
        float w0 = 1.0f / (1.0f + z);
        float w1 = z * w0;
        g_pick_e[warp * 2 + 0] = i0;  g_pick_w[warp * 2 + 0] = w0;
        g_pick_e[warp * 2 + 1] = i1;  g_pick_w[warp * 2 + 1] = w1;
        atomicAdd(&g_cnt[i0], 1);
        atomicAdd(&g_cnt[i1], 1);
    }
}

__global__ void offsets_kernel() {
    int s = 0;
#pragma unroll
    for (int e = 0; e < NEXP; e++) { g_off[e] = s; s += g_cnt[e]; }
}

__global__ void scatter_kernel() {
    int t = blockIdx.x * blockDim.x + threadIdx.x;
    if (t >= NTOK) return;
#pragma unroll
    for (int k = 0; k < TOPK; k++) {
        int e   = g_pick_e[t * 2 + k];
        int pos = atomicAdd(&g_cursor[e], 1);
        int row = g_off[e] + pos;
        g_tok[row]  = t;
        g_gate[row] = g_pick_w[t * 2 + k];
    }
}

// ---------------------------------------------------------------------------
// GEMM compute core: single-pass fp16 (A·B), fp32 accum
// ---------------------------------------------------------------------------
__device__ __forceinline__ void gemm_chunk_compute(
    uint32_t st, int warpM, int warpN, int lane, float acc[2][8][4]) {
    uint32_t sA = st, sB = st + ABYTES;
    int r16 = lane & 15;
    int c8  = (lane >> 4) * 8;
#pragma unroll
    for (int ks = 0; ks < 2; ks++) {
        int kb = ks * 16 + c8;
        uint32_t ah[2][4], bb[8][2];
#pragma unroll
        for (int mf = 0; mf < 2; mf++) {
            uint32_t off = ((warpM * 32 + mf * 16 + r16) * PAD + kb) * 2;
            LDSM4(ah[mf][0], ah[mf][1], ah[mf][2], ah[mf][3], sA + off);
        }
#pragma unroll
        for (int nq = 0; nq < 4; nq++) {
            uint32_t off = ((warpN * 64 + nq * 16 + r16) * PAD + kb) * 2;
            uint32_t r0, r1, r2, r3;
            LDSM4(r0, r1, r2, r3, sB + off);
            bb[2 * nq][0] = r0; bb[2 * nq][1] = r2;
            bb[2 * nq + 1][0] = r1; bb[2 * nq + 1][1] = r3;
        }
#pragma unroll
        for (int mf = 0; mf < 2; mf++)
#pragma unroll
            for (int nf = 0; nf < 8; nf++)
                MMA16816(acc[mf][nf], ah[mf], bb[nf][0], bb[nf][1]);
    }
}

// ---------------------------------------------------------------------------
// GEMM1: hidden = relu(x[tok] @ w1[e] + b1[e]); emit fp16
// ---------------------------------------------------------------------------
__global__ __launch_bounds__(256)
void gemm1_mma(const float* __restrict__ b1) {
    int e = blockIdx.z;
    int cnt = g_cnt[e];
    int tm = blockIdx.y;
    if (tm * TILE >= cnt) return;
    int tn = blockIdx.x;
    int base = g_off[e];

    extern __shared__ __align__(16) char dyn[];
    __shared__ int s_tok[TILE];
    int tid = threadIdx.x, wid = tid >> 5, lane = tid & 31;
    int warpM = wid & 3, warpN = wid >> 2;

    if (tid < TILE) {
        int m = tm * TILE + tid;
        if (m >= cnt) m = cnt - 1;
        s_tok[tid] = g_tok[base + m];
    }
    __syncthreads();

    uint32_t sb = smem_u32(dyn);
    const __half* Bhg = g_w1h + (size_t)e * FFN * DMODEL + (size_t)tn * TILE * DMODEL;

    int r0c = tid >> 2,          j0 = tid & 3;
    int r1c = (tid + 256) >> 2,  j1 = (tid + 256) & 3;

    auto load_chunk = [&](int ch, int s) {
        uint32_t st = sb + s * STAGE;
        int koff = ch * BK;
        {
            uint32_t so = (r0c * PAD + j0 * 8) * 2;
            CPA16(st + so,          g_xh + (size_t)s_tok[r0c] * DMODEL + koff + j0 * 8);
            CPA16(st + ABYTES + so, Bhg + (size_t)r0c * DMODEL + koff + j0 * 8);
        }
        {
            uint32_t so = (r1c * PAD + j1 * 8) * 2;
            CPA16(st + so,          g_xh + (size_t)s_tok[r1c] * DMODEL + koff + j1 * 8);
            CPA16(st + ABYTES + so, Bhg + (size_t)r1c * DMODEL + koff + j1 * 8);
        }
    };

    float acc[2][8][4];
#pragma unroll
    for (int i = 0; i < 2; i++)
#pragma unroll
        for (int j = 0; j < 8; j++)
#pragma unroll
            for (int c = 0; c < 4; c++) acc[i][j][c] = 0.f;

    const int NCH = DMODEL / BK;   // 16
    load_chunk(0, 0); CP_COMMIT();
    load_chunk(1, 1); CP_COMMIT();
    for (int c = 0; c < NCH; c++) {
        if (c + 2 < NCH) load_chunk(c + 2, (c + 2) % NSTG);
        CP_COMMIT();
        CP_WAIT2();
        __syncthreads();
        gemm_chunk_compute(sb + (c % NSTG) * STAGE, warpM, warpN, lane, acc);
        __syncthreads();
    }

    // epilogue: bias + relu -> fp16
    int group = lane >> 2, tid4 = lane & 3;
#pragma unroll
    for (int mf = 0; mf < 2; mf++) {
#pragma unroll
        for (int half = 0; half < 2; half++) {
            int m = tm * TILE + warpM * 32 + mf * 16 + group + half * 8;
            if (m < cnt) {
                size_t hrow = (size_t)(base + m) * FFN;
#pragma unroll
                for (int nf = 0; nf < 8; nf++) {
                    int col = tn * TILE + warpN * 64 + nf * 8 + tid4 * 2;
                    float v0 = fmaxf(acc[mf][nf][half * 2 + 0] + b1[e * FFN + col],     0.f);
                    float v1 = fmaxf(acc[mf][nf][half * 2 + 1] + b1[e * FFN + col + 1], 0.f);
                    *(__half2*)(g_hh + hrow + col) =
                        __halves2half2(__float2half_rn(v0), __float2half_rn(v1));
                }
            }
        }
    }
}

// ---------------------------------------------------------------------------
// GEMM2: out += gate * (hidden @ w2[e] + b2[e])
// ---------------------------------------------------------------------------
__global__ __launch_bounds__(256)
void gemm2_mma(const float* __restrict__ b2, float* __restrict__ out) {
    int e = blockIdx.z;
    int cnt = g_cnt[e];
    int tm = blockIdx.y;
    if (tm * TILE >= cnt) return;
    int tn = blockIdx.x;
    int base = g_off[e];

    extern __shared__ __align__(16) char dyn[];
    __shared__ int s_row[TILE];
    int tid = threadIdx.x, wid = tid >> 5, lane = tid & 31;
    int warpM = wid & 3, warpN = wid >> 2;

    if (tid < TILE) {
        int m = tm * TILE + tid;
        if (m >= cnt) m = cnt - 1;
        s_row[tid] = base + m;
    }
    __syncthreads();

    uint32_t sb = smem_u32(dyn);
    const __half* Bhg = g_w2h + (size_t)e * DMODEL * FFN + (size_t)tn * TILE * FFN;

    int r0c = tid >> 2,          j0 = tid & 3;
    int r1c = (tid + 256) >> 2,  j1 = (tid + 256) & 3;

    auto load_chunk = [&](int ch, int s) {
        uint32_t st = sb + s * STAGE;
        int koff = ch * BK;
        {
            uint32_t so = (r0c * PAD + j0 * 8) * 2;
            CPA16(st + so,          g_hh + (size_t)s_row[r0c] * FFN + koff + j0 * 8);
            CPA16(st + ABYTES + so, Bhg + (size_t)r0c * FFN + koff + j0 * 8);
        }
        {
            uint32_t so = (r1c * PAD + j1 * 8) * 2;
            CPA16(st + so,          g_hh + (size_t)s_row[r1c] * FFN + koff + j1 * 8);
            CPA16(st + ABYTES + so, Bhg + (size_t)r1c * FFN + koff + j1 * 8);
        }
    };

    float acc[2][8][4];
#pragma unroll
    for (int i = 0; i < 2; i++)
#pragma unroll
        for (int j = 0; j < 8; j++)
#pragma unroll
            for (int c = 0; c < 4; c++) acc[i][j][c] = 0.f;

    const int NCH = FFN / BK;   // 64
    load_chunk(0, 0); CP_COMMIT();
    load_chunk(1, 1); CP_COMMIT();
    for (int c = 0; c < NCH; c++) {
        if (c + 2 < NCH) load_chunk(c + 2, (c + 2) % NSTG);
        CP_COMMIT();
        CP_WAIT2();
        __syncthreads();
        gemm_chunk_compute(sb + (c % NSTG) * STAGE, warpM, warpN, lane, acc);
        __syncthreads();
    }

    int group = lane >> 2, tid4 = lane & 3;
#pragma unroll
    for (int mf = 0; mf < 2; mf++) {
#pragma unroll
        for (int half = 0; half < 2; half++) {
            int m = tm * TILE + warpM * 32 + mf * 16 + group + half * 8;
            if (m < cnt) {
                int   token = g_tok[base + m];
                float gate  = g_gate[base + m];
                float* orow = out + (size_t)token * DMODEL;
#pragma unroll
                for (int nf = 0; nf < 8; nf++) {
                    int col = tn * TILE + warpN * 64 + nf * 8 + tid4 * 2;
                    float v0 = (acc[mf][nf][half * 2 + 0] + b2[e * DMODEL + col])     * gate;
                    float v1 = (acc[mf][nf][half * 2 + 1] + b2[e * DMODEL + col + 1]) * gate;
                    atomicAdd(&orow[col],     v0);
                    atomicAdd(&orow[col + 1], v1);
                }
            }
        }
    }
}

// ---------------------------------------------------------------------------
extern "C" void kernel_launch(void* const* d_in, const int* in_sizes, int n_in,
                              void* d_out, int out_size) {
    const float* x   = (const float*)d_in[0];
    const float* rw  = (const float*)d_in[1];
    const float* rb  = (const float*)d_in[2];
    const float* w1  = (const float*)d_in[3];
    const float* b1  = (const float*)d_in[4];
    const float* w2  = (const float*)d_in[5];
    const float* b2  = (const float*)d_in[6];
    float* out = (float*)d_out;

    static bool attr_set = false;
    if (!attr_set) {
        cudaFuncSetAttribute(gemm1_mma, cudaFuncAttributeMaxDynamicSharedMemorySize, DSMEM);
        cudaFuncSetAttribute(gemm2_mma, cudaFuncAttributeMaxDynamicSharedMemorySize, DSMEM);
        attr_set = true;
    }

    zero_kernel<<<1024, 256>>>(out, NTOK * DMODEL);
    convert_x_kernel<<<1024, 256>>>(x);
    transconv_w1_kernel<<<dim3(FFN / 32, DMODEL / 32, NEXP), dim3(32, 8)>>>(w1);
    transconv_w2_kernel<<<dim3(DMODEL / 32, FFN / 32, NEXP), dim3(32, 8)>>>(w2);

    router_kernel<<<(NTOK * 32) / 256, 256>>>(x, rw, rb);
    offsets_kernel<<<1, 1>>>();
    scatter_kernel<<<NTOK / 256, 256>>>();

    gemm1_mma<<<dim3(FFN / TILE, NTOK / TILE, NEXP), 256, DSMEM>>>(b1);
    gemm2_mma<<<dim3(DMODEL / TILE, NTOK / TILE, NEXP), 256, DSMEM>>>(b2, out);
}

// round 10
// speedup vs baseline: 5.2609x; 1.1397x over previous
#include <cuda_runtime.h>
#include <cuda_fp16.h>
#include <cstdint>

// Problem constants
#define DMODEL 512
#define FFN    2048
#define NEXP   8
#define TOPK   2
#define NTOK   8192
#define NROWS  (NTOK * TOPK)
#define TILE   128
#define BK     64          // fp16 K elems per smem chunk (was 32)
#define PAD    72          // smem row stride in fp16 (144 B, conflict-free, 16B-aligned)

#define ABYTES (TILE * PAD * 2)      // 18432 B per array
#define STAGE  (2 * ABYTES)          // A|B per stage = 36864 B
#define NSTG   3
#define DSMEM  (NSTG * STAGE)        // 110592 B dynamic smem

// ---------------------------------------------------------------------------
// Device scratch (static).
// ---------------------------------------------------------------------------
__device__ __half g_xh[(size_t)NTOK * DMODEL];
__device__ __half g_w1h[(size_t)NEXP * FFN * DMODEL];   // [E][F][D] transposed, fp16
__device__ __half g_w2h[(size_t)NEXP * DMODEL * FFN];   // [E][D][F] transposed, fp16
__device__ __half g_hh[(size_t)NROWS * FFN];
__device__ int   g_cnt[NEXP];
__device__ int   g_off[NEXP];
__device__ int   g_cursor[NEXP];
__device__ int   g_tok[NROWS];
__device__ float g_gate[NROWS];
__device__ int   g_pick_e[NROWS];
__device__ float g_pick_w[NROWS];

// ---------------------------------------------------------------------------
__device__ __forceinline__ uint32_t smem_u32(const void* p) {
    uint32_t a;
    asm("{ .reg .u64 t; cvta.to.shared.u64 t, %1; cvt.u32.u64 %0, t; }" : "=r"(a) : "l"(p));
    return a;
}

#define LDSM4(R0, R1, R2, R3, ADDR) \
    asm volatile("ldmatrix.sync.aligned.m8n8.x4.shared.b16 {%0,%1,%2,%3}, [%4];" \
                 : "=r"(R0), "=r"(R1), "=r"(R2), "=r"(R3) : "r"(ADDR))

#define MMA16816(C, A, B0, B1) \
    asm volatile("mma.sync.aligned.m16n8k16.row.col.f32.f16.f16.f32 " \
                 "{%0,%1,%2,%3}, {%4,%5,%6,%7}, {%8,%9}, {%0,%1,%2,%3};" \
                 : "+f"((C)[0]), "+f"((C)[1]), "+f"((C)[2]), "+f"((C)[3]) \
                 : "r"((A)[0]), "r"((A)[1]), "r"((A)[2]), "r"((A)[3]), "r"(B0), "r"(B1))

#define CPA16(DST, SRC) \
    asm volatile("cp.async.cg.shared.global [%0], [%1], 16;" :: "r"(DST), "l"(SRC))
#define CP_COMMIT() asm volatile("cp.async.commit_group;")
#define CP_WAIT2()  asm volatile("cp.async.wait_group 2;")

// ---------------------------------------------------------------------------
__global__ void zero_kernel(float* __restrict__ out, int n) {
    int i = blockIdx.x * blockDim.x + threadIdx.x;
    if (i < NEXP) { g_cnt[i] = 0; g_cursor[i] = 0; }
    float4* o4 = (float4*)out;
    int n4 = n >> 2;
    float4 z = make_float4(0.f, 0.f, 0.f, 0.f);
    for (int j = i; j < n4; j += gridDim.x * blockDim.x) o4[j] = z;
}

// x -> fp16
__global__ void convert_x_kernel(const float* __restrict__ x) {
    int tot = NTOK * DMODEL / 4;
    for (int i = blockIdx.x * blockDim.x + threadIdx.x; i < tot; i += gridDim.x * blockDim.x) {
        float4 v = ((const float4*)x)[i];
        __half2* ph = (__half2*)(g_xh + (size_t)i * 4);
        ph[0] = __halves2half2(__float2half_rn(v.x), __float2half_rn(v.y));
        ph[1] = __halves2half2(__float2half_rn(v.z), __float2half_rn(v.w));
    }
}

// Transpose-convert: w [E][K][N] fp32 -> oh [E][N][K] fp16
__device__ __forceinline__ void transconv_body(const float* __restrict__ w,
                                               __half* __restrict__ oh,
                                               int K, int N) {
    __shared__ float t[32][33];
    int e = blockIdx.z;
    const float* we = w + (size_t)e * K * N;
    int n0 = blockIdx.x * 32, k0 = blockIdx.y * 32;
    int tx = threadIdx.x, ty = threadIdx.y;
    for (int i = ty; i < 32; i += 8)
        t[i][tx] = we[(size_t)(k0 + i) * N + n0 + tx];
    __syncthreads();
    size_t ob = (size_t)e * N * K;
    for (int i = ty; i < 32; i += 8)
        oh[ob + (size_t)(n0 + i) * K + k0 + tx] = __float2half_rn(t[tx][i]);
}
__global__ void transconv_w1_kernel(const float* __restrict__ w1) {
    transconv_body(w1, g_w1h, DMODEL, FFN);
}
__global__ void transconv_w2_kernel(const float* __restrict__ w2) {
    transconv_body(w2, g_w2h, FFN, DMODEL);
}

// ---------------------------------------------------------------------------
// Router / offsets / scatter (validated)
// ---------------------------------------------------------------------------
__global__ void router_kernel(const float* __restrict__ x,
                              const float* __restrict__ rw,
                              const float* __restrict__ rb) {
    int warp = (blockIdx.x * blockDim.x + threadIdx.x) >> 5;
    int lane = threadIdx.x & 31;
    if (warp >= NTOK) return;
    const float* xr = x + (size_t)warp * DMODEL;
    float acc[NEXP];
#pragma unroll
    for (int e = 0; e < NEXP; e++) acc[e] = 0.0f;
    for (int d = lane; d < DMODEL; d += 32) {
        float xv = xr[d];
#pragma unroll
        for (int e = 0; e < NEXP; e++) acc[e] += xv * rw[d * NEXP + e];
    }
#pragma unroll
    for (int e = 0; e < NEXP; e++) {
#pragma unroll
        for (int o = 16; o > 0; o >>= 1) acc[e] += __shfl_xor_sync(0xffffffffu, acc[e], o);
    }
    if (lane == 0) {
        float l[NEXP];
#pragma unroll
        for (int e = 0; e < NEXP; e++) l[e] = acc[e] + rb[e];
        int i0 = 0;
#pragma unroll
        for (int e = 1; e < NEXP; e++) if (l[e] > l[i0]) i0 = e;
        int i1 = -1;
#pragma unroll
        for (int e = 0; e < NEXP; e++) {
            if (e == i0) continue;
            if (i1 < 0 || l[e] > l[i1]) i1 = e;
        }
        float z  = expf(l[i1] - l[i0]);
        float w0 = 1.0f / (1.0f + z);
        float w1 = z * w0;
        g_pick_e[warp * 2 + 0] = i0;  g_pick_w[warp * 2 + 0] = w0;
        g_pick_e[warp * 2 + 1] = i1;  g_pick_w[warp * 2 + 1] = w1;
        atomicAdd(&g_cnt[i0], 1);
        atomicAdd(&g_cnt[i1], 1);
    }
}

__global__ void offsets_kernel() {
    int s = 0;
#pragma unroll
    for (int e = 0; e < NEXP; e++) { g_off[e] = s; s += g_cnt[e]; }
}

__global__ void scatter_kernel() {
    int t = blockIdx.x * blockDim.x + threadIdx.x;
    if (t >= NTOK) return;
#pragma unroll
    for (int k = 0; k < TOPK; k++) {
        int e   = g_pick_e[t * 2 + k];
        int pos = atomicAdd(&g_cursor[e], 1);
        int row = g_off[e] + pos;
        g_tok[row]  = t;
        g_gate[row] = g_pick_w[t * 2 + k];
    }
}

// ---------------------------------------------------------------------------
// GEMM compute core: single-pass fp16, 4 k16 slabs per chunk (BK=64)
// ---------------------------------------------------------------------------
__device__ __forceinline__ void gemm_chunk_compute(
    uint32_t st, int warpM, int warpN, int lane, float acc[2][8][4]) {
    uint32_t sA = st, sB = st + ABYTES;
    int r16 = lane & 15;
    int c8  = (lane >> 4) * 8;
#pragma unroll
    for (int ks = 0; ks < 4; ks++) {
        int kb = ks * 16 + c8;
        uint32_t ah[2][4], bb[8][2];
#pragma unroll
        for (int mf = 0; mf < 2; mf++) {
            uint32_t off = ((warpM * 32 + mf * 16 + r16) * PAD + kb) * 2;
            LDSM4(ah[mf][0], ah[mf][1], ah[mf][2], ah[mf][3], sA + off);
        }
#pragma unroll
        for (int nq = 0; nq < 4; nq++) {
            uint32_t off = ((warpN * 64 + nq * 16 + r16) * PAD + kb) * 2;
            uint32_t r0, r1, r2, r3;
            LDSM4(r0, r1, r2, r3, sB + off);
            bb[2 * nq][0] = r0; bb[2 * nq][1] = r2;
            bb[2 * nq + 1][0] = r1; bb[2 * nq + 1][1] = r3;
        }
#pragma unroll
        for (int mf = 0; mf < 2; mf++)
#pragma unroll
            for (int nf = 0; nf < 8; nf++)
                MMA16816(acc[mf][nf], ah[mf], bb[nf][0], bb[nf][1]);
    }
}

// ---------------------------------------------------------------------------
// GEMM1: hidden = relu(x[tok] @ w1[e] + b1[e]); emit fp16
// ---------------------------------------------------------------------------
__global__ __launch_bounds__(256)
void gemm1_mma(const float* __restrict__ b1) {
    int e = blockIdx.z;
    int cnt = g_cnt[e];
    int tm = blockIdx.y;
    if (tm * TILE >= cnt) return;
    int tn = blockIdx.x;
    int base = g_off[e];

    extern __shared__ __align__(16) char dyn[];
    __shared__ int s_tok[TILE];
    int tid = threadIdx.x, wid = tid >> 5, lane = tid & 31;
    int warpM = wid & 3, warpN = wid >> 2;

    if (tid < TILE) {
        int m = tm * TILE + tid;
        if (m >= cnt) m = cnt - 1;
        s_tok[tid] = g_tok[base + m];
    }
    __syncthreads();

    uint32_t sb = smem_u32(dyn);
    const __half* Bhg = g_w1h + (size_t)e * FFN * DMODEL + (size_t)tn * TILE * DMODEL;

    // 4 copy slots per array per thread (128 rows x 8 col-units = 1024 / 256)
    auto load_chunk = [&](int ch, int s) {
        uint32_t st = sb + s * STAGE;
        int koff = ch * BK;
#pragma unroll
        for (int q = 0; q < 4; q++) {
            int u = tid + q * 256;
            int r = u >> 3, j = u & 7;
            uint32_t so = (r * PAD + j * 8) * 2;
            CPA16(st + so,          g_xh + (size_t)s_tok[r] * DMODEL + koff + j * 8);
            CPA16(st + ABYTES + so, Bhg + (size_t)r * DMODEL + koff + j * 8);
        }
    };

    float acc[2][8][4];
#pragma unroll
    for (int i = 0; i < 2; i++)
#pragma unroll
        for (int j = 0; j < 8; j++)
#pragma unroll
            for (int c = 0; c < 4; c++) acc[i][j][c] = 0.f;

    const int NCH = DMODEL / BK;   // 8
    load_chunk(0, 0); CP_COMMIT();
    load_chunk(1, 1); CP_COMMIT();
    for (int c = 0; c < NCH; c++) {
        if (c + 2 < NCH) load_chunk(c + 2, (c + 2) % NSTG);
        CP_COMMIT();
        CP_WAIT2();
        __syncthreads();
        gemm_chunk_compute(sb + (c % NSTG) * STAGE, warpM, warpN, lane, acc);
        __syncthreads();
    }

    // epilogue: bias + relu -> fp16
    int group = lane >> 2, tid4 = lane & 3;
#pragma unroll
    for (int mf = 0; mf < 2; mf++) {
#pragma unroll
        for (int half = 0; half < 2; half++) {
            int m = tm * TILE + warpM * 32 + mf * 16 + group + half * 8;
            if (m < cnt) {
                size_t hrow = (size_t)(base + m) * FFN;
#pragma unroll
                for (int nf = 0; nf < 8; nf++) {
                    int col = tn * TILE + warpN * 64 + nf * 8 + tid4 * 2;
                    float v0 = fmaxf(acc[mf][nf][half * 2 + 0] + b1[e * FFN + col],     0.f);
                    float v1 = fmaxf(acc[mf][nf][half * 2 + 1] + b1[e * FFN + col + 1], 0.f);
                    *(__half2*)(g_hh + hrow + col) =
                        __halves2half2(__float2half_rn(v0), __float2half_rn(v1));
                }
            }
        }
    }
}

// ---------------------------------------------------------------------------
// GEMM2: out += gate * (hidden @ w2[e] + b2[e])
// ---------------------------------------------------------------------------
__global__ __launch_bounds__(256)
void gemm2_mma(const float* __restrict__ b2, float* __restrict__ out) {
    int e = blockIdx.z;
    int cnt = g_cnt[e];
    int tm = blockIdx.y;
    if (tm * TILE >= cnt) return;
    int tn = blockIdx.x;
    int base = g_off[e];

    extern __shared__ __align__(16) char dyn[];
    __shared__ int s_row[TILE];
    int tid = threadIdx.x, wid = tid >> 5, lane = tid & 31;
    int warpM = wid & 3, warpN = wid >> 2;

    if (tid < TILE) {
        int m = tm * TILE + tid;
        if (m >= cnt) m = cnt - 1;
        s_row[tid] = base + m;
    }
    __syncthreads();

    uint32_t sb = smem_u32(dyn);
    const __half* Bhg = g_w2h + (size_t)e * DMODEL * FFN + (size_t)tn * TILE * FFN;

    auto load_chunk = [&](int ch, int s) {
        uint32_t st = sb + s * STAGE;
        int koff = ch * BK;
#pragma unroll
        for (int q = 0; q < 4; q++) {
            int u = tid + q * 256;
            int r = u >> 3, j = u & 7;
            uint32_t so = (r * PAD + j * 8) * 2;
            CPA16(st + so,          g_hh + (size_t)s_row[r] * FFN + koff + j * 8);
            CPA16(st + ABYTES + so, Bhg + (size_t)r * FFN + koff + j * 8);
        }
    };

    float acc[2][8][4];
#pragma unroll
    for (int i = 0; i < 2; i++)
#pragma unroll
        for (int j = 0; j < 8; j++)
#pragma unroll
            for (int c = 0; c < 4; c++) acc[i][j][c] = 0.f;

    const int NCH = FFN / BK;   // 32
    load_chunk(0, 0); CP_COMMIT();
    load_chunk(1, 1); CP_COMMIT();
    for (int c = 0; c < NCH; c++) {
        if (c + 2 < NCH) load_chunk(c + 2, (c + 2) % NSTG);
        CP_COMMIT();
        CP_WAIT2();
        __syncthreads();
        gemm_chunk_compute(sb + (c % NSTG) * STAGE, warpM, warpN, lane, acc);
        __syncthreads();
    }

    int group = lane >> 2, tid4 = lane & 3;
#pragma unroll
    for (int mf = 0; mf < 2; mf++) {
#pragma unroll
        for (int half = 0; half < 2; half++) {
            int m = tm * TILE + warpM * 32 + mf * 16 + group + half * 8;
            if (m < cnt) {
                int   token = g_tok[base + m];
                float gate  = g_gate[base + m];
                float* orow = out + (size_t)token * DMODEL;
#pragma unroll
                for (int nf = 0; nf < 8; nf++) {
                    int col = tn * TILE + warpN * 64 + nf * 8 + tid4 * 2;
                    float v0 = (acc[mf][nf][half * 2 + 0] + b2[e * DMODEL + col])     * gate;
                    float v1 = (acc[mf][nf][half * 2 + 1] + b2[e * DMODEL + col + 1]) * gate;
                    atomicAdd(&orow[col],     v0);
                    atomicAdd(&orow[col + 1], v1);
                }
            }
        }
    }
}

// ---------------------------------------------------------------------------
extern "C" void kernel_launch(void* const* d_in, const int* in_sizes, int n_in,
                              void* d_out, int out_size) {
    const float* x   = (const float*)d_in[0];
    const float* rw  = (const float*)d_in[1];
    const float* rb  = (const float*)d_in[2];
    const float* w1  = (const float*)d_in[3];
    const float* b1  = (const float*)d_in[4];
    const float* w2  = (const float*)d_in[5];
    const float* b2  = (const float*)d_in[6];
    float* out = (float*)d_out;

    static bool attr_set = false;
    if (!attr_set) {
        cudaFuncSetAttribute(gemm1_mma, cudaFuncAttributeMaxDynamicSharedMemorySize, DSMEM);
        cudaFuncSetAttribute(gemm2_mma, cudaFuncAttributeMaxDynamicSharedMemorySize, DSMEM);
        attr_set = true;
    }

    zero_kernel<<<1024, 256>>>(out, NTOK * DMODEL);
    convert_x_kernel<<<1024, 256>>>(x);
    transconv_w1_kernel<<<dim3(FFN / 32, DMODEL / 32, NEXP), dim3(32, 8)>>>(w1);
    transconv_w2_kernel<<<dim3(DMODEL / 32, FFN / 32, NEXP), dim3(32, 8)>>>(w2);

    router_kernel<<<(NTOK * 32) / 256, 256>>>(x, rw, rb);
    offsets_kernel<<<1, 1>>>();
    scatter_kernel<<<NTOK / 256, 256>>>();

    gemm1_mma<<<dim3(FFN / TILE, NTOK / TILE, NEXP), 256, DSMEM>>>(b1);
    gemm2_mma<<<dim3(DMODEL / TILE, NTOK / TILE, NEXP), 256, DSMEM>>>(b2, out);
}